// round 2
// baseline (speedup 1.0000x reference)
#include <cuda_runtime.h>
#include <cuda_bf16.h>
#include <cstdint>

#define B_   2
#define S_   2048
#define D_   1024
#define H_   16
#define DH_  64
#define FF_  2048
#define N_   (B_*S_)     // 4096
#define EPS_ 1e-6f

#define FLAG_RELU 1
#define FLAG_HEAD 2

// ---------------- scratch (allocation-free) ----------------
__device__ float g_q[N_ * D_];     // [B,H,S,Dh]
__device__ float g_k[N_ * D_];
__device__ float g_v[N_ * D_];
__device__ float g_ctx[N_ * D_];   // [N, D]
__device__ float g_x0[N_ * D_];
__device__ float g_x1[N_ * D_];
__device__ float g_ff[N_ * FF_];

// ---------------- 128x128x8 double-buffered SGEMM ----------------
// C[n,m] = sum_k A[n,k] * W[m,k] + bias[m] (+ residual[n,m]) ; optional relu
// 256 threads, 8x8 per thread (4+4 split), reg-prefetch + smem double buffer.
__global__ __launch_bounds__(256, 2)
void gemm128(const float* __restrict__ A, const float* __restrict__ W,
             const float* __restrict__ bias, const float* __restrict__ residual,
             float* __restrict__ C, int N, int M, int K, int flags)
{
    __shared__ float As[2][8][132];
    __shared__ float Ws[2][8][132];
    const int t  = threadIdx.x;
    const int tx = t & 15, ty = t >> 4;
    const int n0 = blockIdx.y * 128, m0 = blockIdx.x * 128;

    const int lr = t >> 1;          // 0..127: row within tile
    const int lk = (t & 1) * 4;     // 0 or 4: k-offset within BK=8

    const float* Aptr = A + (size_t)(n0 + lr) * K + lk;
    const float* Wptr = W + (size_t)(m0 + lr) * K + lk;

    {   // stage 0
        float4 a = *(const float4*)Aptr;
        float4 w = *(const float4*)Wptr;
        As[0][lk+0][lr] = a.x; As[0][lk+1][lr] = a.y; As[0][lk+2][lr] = a.z; As[0][lk+3][lr] = a.w;
        Ws[0][lk+0][lr] = w.x; Ws[0][lk+1][lr] = w.y; Ws[0][lk+2][lr] = w.z; Ws[0][lk+3][lr] = w.w;
    }
    __syncthreads();

    float acc[8][8];
#pragma unroll
    for (int i = 0; i < 8; i++)
#pragma unroll
        for (int j = 0; j < 8; j++) acc[i][j] = 0.f;

    int buf = 0;
    for (int k0 = 8; k0 <= K; k0 += 8) {
        const bool has_next = (k0 < K);
        float4 an, wn;
        if (has_next) {                    // issue global loads early (overlap compute)
            an = *(const float4*)(Aptr + k0);
            wn = *(const float4*)(Wptr + k0);
        }
#pragma unroll
        for (int kk = 0; kk < 8; kk++) {
            float4 a0 = *(const float4*)&As[buf][kk][ty * 4];
            float4 a1 = *(const float4*)&As[buf][kk][64 + ty * 4];
            float4 b0 = *(const float4*)&Ws[buf][kk][tx * 4];
            float4 b1 = *(const float4*)&Ws[buf][kk][64 + tx * 4];
            float av[8] = {a0.x, a0.y, a0.z, a0.w, a1.x, a1.y, a1.z, a1.w};
            float bv[8] = {b0.x, b0.y, b0.z, b0.w, b1.x, b1.y, b1.z, b1.w};
#pragma unroll
            for (int i = 0; i < 8; i++)
#pragma unroll
                for (int j = 0; j < 8; j++) acc[i][j] += av[i] * bv[j];
        }
        if (has_next) {
            buf ^= 1;
            As[buf][lk+0][lr] = an.x; As[buf][lk+1][lr] = an.y; As[buf][lk+2][lr] = an.z; As[buf][lk+3][lr] = an.w;
            Ws[buf][lk+0][lr] = wn.x; Ws[buf][lk+1][lr] = wn.y; Ws[buf][lk+2][lr] = wn.z; Ws[buf][lk+3][lr] = wn.w;
            __syncthreads();
        }
    }

#pragma unroll
    for (int i = 0; i < 8; i++) {
        int n = n0 + ((i < 4) ? (ty * 4 + i) : (64 + ty * 4 + i - 4));
#pragma unroll
        for (int j = 0; j < 8; j++) {
            int m = m0 + ((j < 4) ? (tx * 4 + j) : (64 + tx * 4 + j - 4));
            float v = acc[i][j] + bias[m];
            if (residual) v += residual[(size_t)n * M + m];
            if (flags & FLAG_RELU) v = fmaxf(v, 0.f);
            if (flags & FLAG_HEAD) {
                int b = n >> 11, s = n & 2047;
                int h = m >> 6,  dh = m & 63;
                C[(((size_t)(b * H_ + h)) * S_ + s) * DH_ + dh] = v;
            } else {
                C[(size_t)n * M + m] = v;
            }
        }
    }
}

// ---------------- flash attention ----------------
__device__ __forceinline__ float redmax16(float v) {
#pragma unroll
    for (int off = 8; off; off >>= 1) v = fmaxf(v, __shfl_xor_sync(0xffffffffu, v, off, 16));
    return v;
}
__device__ __forceinline__ float redsum16(float v) {
#pragma unroll
    for (int off = 8; off; off >>= 1) v += __shfl_xor_sync(0xffffffffu, v, off, 16);
    return v;
}

#define FA_SMEM (4 * 64 * 68 * 4)

__global__ void flash_attn_kernel(const float* __restrict__ q, const float* __restrict__ k,
                                  const float* __restrict__ v, const int* __restrict__ mask,
                                  float* __restrict__ ctx)
{
    extern __shared__ float sm[];
    float* QsT = sm;                 // [d=64][r=64] pitch 68
    float* KsT = sm + 64 * 68;       // [d][kc]
    float* Vs  = sm + 2 * 64 * 68;   // [key][c]
    float* PsT = sm + 3 * 64 * 68;   // [key][qr]

    const int t = threadIdx.x, tx = t & 15, ty = t >> 4;
    const int bh = blockIdx.y, b = bh >> 4, h = bh & 15;
    const int q0 = blockIdx.x * 64;
    const float* qh = q + (size_t)bh * S_ * DH_;
    const float* kh = k + (size_t)bh * S_ * DH_;
    const float* vh = v + (size_t)bh * S_ * DH_;
    const int* maskb = mask + (size_t)b * S_ * S_;

#pragma unroll
    for (int i = 0; i < 16; i++) {
        int idx = t + i * 256;
        int r = idx >> 6, d = idx & 63;
        QsT[d * 68 + r] = qh[(size_t)(q0 + r) * 64 + d];
    }

    float acc[4][4];
#pragma unroll
    for (int i = 0; i < 4; i++)
#pragma unroll
        for (int j = 0; j < 4; j++) acc[i][j] = 0.f;
    float mrow[4] = {-1e30f, -1e30f, -1e30f, -1e30f};
    float lrow[4] = {0.f, 0.f, 0.f, 0.f};

    for (int k0 = 0; k0 < S_; k0 += 64) {
        __syncthreads();   // prev PV done (and Q load visible on first iter)
#pragma unroll
        for (int i = 0; i < 16; i++) {
            int idx = t + i * 256;
            int r = idx >> 6, d = idx & 63;
            float kv = kh[(size_t)(k0 + r) * 64 + d];
            KsT[d * 68 + r] = kv;
            Vs[r * 68 + d]  = vh[(size_t)(k0 + r) * 64 + d];
        }
        __syncthreads();

        float s[4][4];
#pragma unroll
        for (int i = 0; i < 4; i++)
#pragma unroll
            for (int j = 0; j < 4; j++) s[i][j] = 0.f;
        for (int d = 0; d < 64; d++) {
            float4 a = *(const float4*)&QsT[d * 68 + ty * 4];
            float4 bb = *(const float4*)&KsT[d * 68 + tx * 4];
            s[0][0] += a.x * bb.x; s[0][1] += a.x * bb.y; s[0][2] += a.x * bb.z; s[0][3] += a.x * bb.w;
            s[1][0] += a.y * bb.x; s[1][1] += a.y * bb.y; s[1][2] += a.y * bb.z; s[1][3] += a.y * bb.w;
            s[2][0] += a.z * bb.x; s[2][1] += a.z * bb.y; s[2][2] += a.z * bb.z; s[2][3] += a.z * bb.w;
            s[3][0] += a.w * bb.x; s[3][1] += a.w * bb.y; s[3][2] += a.w * bb.z; s[3][3] += a.w * bb.w;
        }

#pragma unroll
        for (int i = 0; i < 4; i++) {
            int qr = q0 + ty * 4 + i;
#pragma unroll
            for (int j = 0; j < 4; j++) {
                float val = s[i][j] * 0.125f;
                int mv = maskb[(size_t)qr * S_ + k0 + tx * 4 + j];
                if (mv == 0) val = -1e9f;
                s[i][j] = val;
            }
        }

#pragma unroll
        for (int i = 0; i < 4; i++) {
            float mx = fmaxf(fmaxf(s[i][0], s[i][1]), fmaxf(s[i][2], s[i][3]));
            mx = redmax16(mx);
            float mnew = fmaxf(mrow[i], mx);
            float corr = __expf(mrow[i] - mnew);
            mrow[i] = mnew;
            float rs = 0.f;
#pragma unroll
            for (int j = 0; j < 4; j++) {
                s[i][j] = __expf(s[i][j] - mnew);
                rs += s[i][j];
            }
            rs = redsum16(rs);
            lrow[i] = lrow[i] * corr + rs;
#pragma unroll
            for (int j = 0; j < 4; j++) acc[i][j] *= corr;
        }

#pragma unroll
        for (int i = 0; i < 4; i++)
#pragma unroll
            for (int j = 0; j < 4; j++)
                PsT[(tx * 4 + j) * 68 + ty * 4 + i] = s[i][j];
        __syncthreads();

        for (int kk = 0; kk < 64; kk++) {
            float4 a = *(const float4*)&PsT[kk * 68 + ty * 4];
            float4 bb = *(const float4*)&Vs[kk * 68 + tx * 4];
            acc[0][0] += a.x * bb.x; acc[0][1] += a.x * bb.y; acc[0][2] += a.x * bb.z; acc[0][3] += a.x * bb.w;
            acc[1][0] += a.y * bb.x; acc[1][1] += a.y * bb.y; acc[1][2] += a.y * bb.z; acc[1][3] += a.y * bb.w;
            acc[2][0] += a.z * bb.x; acc[2][1] += a.z * bb.y; acc[2][2] += a.z * bb.z; acc[2][3] += a.z * bb.w;
            acc[3][0] += a.w * bb.x; acc[3][1] += a.w * bb.y; acc[3][2] += a.w * bb.z; acc[3][3] += a.w * bb.w;
        }
    }

#pragma unroll
    for (int i = 0; i < 4; i++) {
        float inv = 1.f / lrow[i];
        int n = b * S_ + q0 + ty * 4 + i;
#pragma unroll
        for (int j = 0; j < 4; j++) {
            int c = h * 64 + tx * 4 + j;
            ctx[(size_t)n * D_ + c] = acc[i][j] * inv;
        }
    }
}

// ---------------- layer norm (torch semantics: ddof=1, eps on std) ----------------
__global__ void layernorm_kernel(const float* __restrict__ x, const float* __restrict__ alpha,
                                 const float* __restrict__ beta, float* __restrict__ out)
{
    const int row = blockIdx.x;
    const int t = threadIdx.x;               // 256 threads, 4 floats each
    const float4* xr = (const float4*)(x + (size_t)row * D_);
    float4 v = xr[t];
    float sum = v.x + v.y + v.z + v.w;
    float sq  = v.x * v.x + v.y * v.y + v.z * v.z + v.w * v.w;

    __shared__ float ssum[8], ssq[8];
#pragma unroll
    for (int off = 16; off; off >>= 1) {
        sum += __shfl_xor_sync(0xffffffffu, sum, off);
        sq  += __shfl_xor_sync(0xffffffffu, sq, off);
    }
    int warp = t >> 5, lane = t & 31;
    if (lane == 0) { ssum[warp] = sum; ssq[warp] = sq; }
    __syncthreads();
    float tsum = 0.f, tsq = 0.f;
#pragma unroll
    for (int w = 0; w < 8; w++) { tsum += ssum[w]; tsq += ssq[w]; }

    float mean = tsum * (1.f / D_);
    float var  = (tsq - (float)D_ * mean * mean) * (1.f / (D_ - 1));
    float std_ = sqrtf(fmaxf(var, 0.f));
    float inv  = 1.f / (std_ + EPS_);

    const float4* av = (const float4*)alpha;
    const float4* bv = (const float4*)beta;
    float4 a = av[t], bb = bv[t];
    float4 o;
    o.x = a.x * (v.x - mean) * inv + bb.x;
    o.y = a.y * (v.y - mean) * inv + bb.y;
    o.z = a.z * (v.z - mean) * inv + bb.z;
    o.w = a.w * (v.w - mean) * inv + bb.w;
    ((float4*)(out + (size_t)row * D_))[t] = o;
}

// ---------------- launch ----------------
extern "C" void kernel_launch(void* const* d_in, const int* in_sizes, int n_in,
                              void* d_out, int out_size)
{
    const float* src = (const float*)d_in[0];
    const int*   mask = (const int*)d_in[1];
    const float* Wq = (const float*)d_in[2];
    const float* bq = (const float*)d_in[3];
    const float* Wk = (const float*)d_in[4];
    const float* bk = (const float*)d_in[5];
    const float* Wv = (const float*)d_in[6];
    const float* bv = (const float*)d_in[7];
    const float* Wo = (const float*)d_in[8];
    const float* bo = (const float*)d_in[9];
    const float* W1 = (const float*)d_in[10];
    const float* b1 = (const float*)d_in[11];
    const float* W2 = (const float*)d_in[12];
    const float* b2 = (const float*)d_in[13];
    const float* a1 = (const float*)d_in[14];
    const float* be1 = (const float*)d_in[15];
    const float* a2 = (const float*)d_in[16];
    const float* be2 = (const float*)d_in[17];
    float* out = (float*)d_out;

    void *pq, *pk, *pv, *pctx, *px0, *px1, *pff;
    cudaGetSymbolAddress(&pq, g_q);
    cudaGetSymbolAddress(&pk, g_k);
    cudaGetSymbolAddress(&pv, g_v);
    cudaGetSymbolAddress(&pctx, g_ctx);
    cudaGetSymbolAddress(&px0, g_x0);
    cudaGetSymbolAddress(&px1, g_x1);
    cudaGetSymbolAddress(&pff, g_ff);

    cudaFuncSetAttribute(flash_attn_kernel, cudaFuncAttributeMaxDynamicSharedMemorySize, FA_SMEM);

    dim3 blk(256);
    dim3 gD(D_ / 128, N_ / 128);    // (8, 32)
    dim3 gFF(FF_ / 128, N_ / 128);  // (16, 32)

    // QKV projections, stored directly in [B,H,S,Dh] layout
    gemm128<<<gD, blk>>>(src, Wq, bq, nullptr, (float*)pq, N_, D_, D_, FLAG_HEAD);
    gemm128<<<gD, blk>>>(src, Wk, bk, nullptr, (float*)pk, N_, D_, D_, FLAG_HEAD);
    gemm128<<<gD, blk>>>(src, Wv, bv, nullptr, (float*)pv, N_, D_, D_, FLAG_HEAD);

    // attention -> ctx in [N, D] layout
    flash_attn_kernel<<<dim3(S_ / 64, B_ * H_), blk, FA_SMEM>>>(
        (const float*)pq, (const float*)pk, (const float*)pv, mask, (float*)pctx);

    // output projection + residual(src)
    gemm128<<<gD, blk>>>((const float*)pctx, Wo, bo, src, (float*)px0, N_, D_, D_, 0);

    // norm1
    layernorm_kernel<<<N_, blk>>>((const float*)px0, a1, be1, (float*)px1);

    // FFN
    gemm128<<<gFF, blk>>>((const float*)px1, W1, b1, nullptr, (float*)pff, N_, FF_, D_, FLAG_RELU);
    gemm128<<<gD, blk>>>((const float*)pff, W2, b2, (const float*)px1, (float*)px0, N_, D_, FF_, 0);

    // norm2 -> out
    layernorm_kernel<<<N_, blk>>>((const float*)px0, a2, be2, out);
}

// round 4
// speedup vs baseline: 1.3265x; 1.3265x over previous
#include <cuda_runtime.h>
#include <cuda_bf16.h>
#include <cstdint>

#define B_   2
#define S_   2048
#define D_   1024
#define H_   16
#define DH_  64
#define FF_  2048
#define N_   (B_*S_)     // 4096
#define EPS_ 1e-6f

#define FLAG_RELU 1
#define FLAG_HEAD 2

// ---------------- scratch (allocation-free) ----------------
__device__ float g_q[N_ * D_];     // [B,H,S,Dh]
__device__ float g_k[N_ * D_];
__device__ float g_v[N_ * D_];
__device__ float g_ctx[N_ * D_];   // [N, D]
__device__ float g_x0[N_ * D_];
__device__ float g_x1[N_ * D_];
__device__ float g_ff[N_ * FF_];

// ---------------- TF32 tensor-core GEMM ----------------
// C[n,m] = sum_k A[n,k] * W[m,k] + bias[m] (+ residual[n,m]) ; optional relu
// 128x128 tile, BK=16, 256 threads (8 warps as 2x4), warp tile 64x32,
// mma.sync.m16n8k8 tf32, double-buffered smem, cvt-to-tf32 fused into STS.

__device__ __forceinline__ uint32_t f2tf32(float x) {
    uint32_t r;
    asm("cvt.rna.tf32.f32 %0, %1;" : "=r"(r) : "f"(x));
    return r;
}

__device__ __forceinline__ void mma_tf32(float c[4], uint32_t a0, uint32_t a1, uint32_t a2, uint32_t a3,
                                         uint32_t b0, uint32_t b1) {
    asm volatile("mma.sync.aligned.m16n8k8.row.col.f32.tf32.tf32.f32 "
                 "{%0,%1,%2,%3}, {%4,%5,%6,%7}, {%8,%9}, {%0,%1,%2,%3};"
                 : "+f"(c[0]), "+f"(c[1]), "+f"(c[2]), "+f"(c[3])
                 : "r"(a0), "r"(a1), "r"(a2), "r"(a3), "r"(b0), "r"(b1));
}

#define PITCH 132

__global__ __launch_bounds__(256)
void gemm_tf32(const float* __restrict__ A, const float* __restrict__ W,
               const float* __restrict__ bias, const float* __restrict__ residual,
               float* __restrict__ C, int N, int M, int K, int flags)
{
    __shared__ uint32_t As[2][16][PITCH];   // [k][n-row]
    __shared__ uint32_t Ws[2][16][PITCH];   // [k][m-row]

    const int t  = threadIdx.x;
    const int w  = t >> 5;
    const int wm = w >> 2;           // 0..1
    const int wn = w & 3;            // 0..3
    const int lane = t & 31;
    const int g  = lane >> 2;        // group 0..7
    const int tg = lane & 3;         // thread-in-group 0..3

    const int n0 = blockIdx.y * 128, m0 = blockIdx.x * 128;

    // loader mapping: r = t>>2 (and +64), kq = t&3 -> float4 at k = 4*kq
    const int lrr = t >> 2;          // 0..63
    const int kq  = t & 3;
    const float* Aptr0 = A + (size_t)(n0 + lrr) * K + kq * 4;
    const float* Aptr1 = A + (size_t)(n0 + lrr + 64) * K + kq * 4;
    const float* Wptr0 = W + (size_t)(m0 + lrr) * K + kq * 4;
    const float* Wptr1 = W + (size_t)(m0 + lrr + 64) * K + kq * 4;

    float acc[4][4][4];
#pragma unroll
    for (int mi = 0; mi < 4; mi++)
#pragma unroll
        for (int ni = 0; ni < 4; ni++)
#pragma unroll
            for (int c = 0; c < 4; c++) acc[mi][ni][c] = 0.f;

    // stage 0
    {
        float4 a0 = *(const float4*)Aptr0;
        float4 a1 = *(const float4*)Aptr1;
        float4 w0 = *(const float4*)Wptr0;
        float4 w1 = *(const float4*)Wptr1;
        As[0][kq*4+0][lrr]    = f2tf32(a0.x); As[0][kq*4+1][lrr]    = f2tf32(a0.y);
        As[0][kq*4+2][lrr]    = f2tf32(a0.z); As[0][kq*4+3][lrr]    = f2tf32(a0.w);
        As[0][kq*4+0][lrr+64] = f2tf32(a1.x); As[0][kq*4+1][lrr+64] = f2tf32(a1.y);
        As[0][kq*4+2][lrr+64] = f2tf32(a1.z); As[0][kq*4+3][lrr+64] = f2tf32(a1.w);
        Ws[0][kq*4+0][lrr]    = f2tf32(w0.x); Ws[0][kq*4+1][lrr]    = f2tf32(w0.y);
        Ws[0][kq*4+2][lrr]    = f2tf32(w0.z); Ws[0][kq*4+3][lrr]    = f2tf32(w0.w);
        Ws[0][kq*4+0][lrr+64] = f2tf32(w1.x); Ws[0][kq*4+1][lrr+64] = f2tf32(w1.y);
        Ws[0][kq*4+2][lrr+64] = f2tf32(w1.z); Ws[0][kq*4+3][lrr+64] = f2tf32(w1.w);
    }
    __syncthreads();

    int buf = 0;
    for (int k0 = 16; k0 <= K; k0 += 16) {
        const bool has_next = (k0 < K);
        float4 na0, na1, nw0, nw1;
        if (has_next) {
            na0 = *(const float4*)(Aptr0 + k0);
            na1 = *(const float4*)(Aptr1 + k0);
            nw0 = *(const float4*)(Wptr0 + k0);
            nw1 = *(const float4*)(Wptr1 + k0);
        }

#pragma unroll
        for (int ks = 0; ks < 2; ks++) {
            const int kb = ks * 8;
            uint32_t af[4][4], bf[4][2];
#pragma unroll
            for (int mi = 0; mi < 4; mi++) {
                const int nb = wm * 64 + mi * 16;
                af[mi][0] = As[buf][kb + tg][nb + g];
                af[mi][1] = As[buf][kb + tg][nb + g + 8];
                af[mi][2] = As[buf][kb + tg + 4][nb + g];
                af[mi][3] = As[buf][kb + tg + 4][nb + g + 8];
            }
#pragma unroll
            for (int ni = 0; ni < 4; ni++) {
                const int mb = wn * 32 + ni * 8;
                bf[ni][0] = Ws[buf][kb + tg][mb + g];
                bf[ni][1] = Ws[buf][kb + tg + 4][mb + g];
            }
#pragma unroll
            for (int mi = 0; mi < 4; mi++)
#pragma unroll
                for (int ni = 0; ni < 4; ni++)
                    mma_tf32(acc[mi][ni], af[mi][0], af[mi][1], af[mi][2], af[mi][3],
                             bf[ni][0], bf[ni][1]);
        }

        if (has_next) {
            buf ^= 1;
            As[buf][kq*4+0][lrr]    = f2tf32(na0.x); As[buf][kq*4+1][lrr]    = f2tf32(na0.y);
            As[buf][kq*4+2][lrr]    = f2tf32(na0.z); As[buf][kq*4+3][lrr]    = f2tf32(na0.w);
            As[buf][kq*4+0][lrr+64] = f2tf32(na1.x); As[buf][kq*4+1][lrr+64] = f2tf32(na1.y);
            As[buf][kq*4+2][lrr+64] = f2tf32(na1.z); As[buf][kq*4+3][lrr+64] = f2tf32(na1.w);
            Ws[buf][kq*4+0][lrr]    = f2tf32(nw0.x); Ws[buf][kq*4+1][lrr]    = f2tf32(nw0.y);
            Ws[buf][kq*4+2][lrr]    = f2tf32(nw0.z); Ws[buf][kq*4+3][lrr]    = f2tf32(nw0.w);
            Ws[buf][kq*4+0][lrr+64] = f2tf32(nw1.x); Ws[buf][kq*4+1][lrr+64] = f2tf32(nw1.y);
            Ws[buf][kq*4+2][lrr+64] = f2tf32(nw1.z); Ws[buf][kq*4+3][lrr+64] = f2tf32(nw1.w);
            __syncthreads();
        }
    }

    // epilogue: c0:(g, tg*2) c1:(g, tg*2+1) c2:(g+8, tg*2) c3:(g+8, tg*2+1)
#pragma unroll
    for (int mi = 0; mi < 4; mi++) {
#pragma unroll
        for (int ni = 0; ni < 4; ni++) {
#pragma unroll
            for (int c = 0; c < 4; c++) {
                int n = n0 + wm * 64 + mi * 16 + g + ((c >> 1) ? 8 : 0);
                int m = m0 + wn * 32 + ni * 8 + tg * 2 + (c & 1);
                float v = acc[mi][ni][c] + bias[m];
                if (residual) v += residual[(size_t)n * M + m];
                if (flags & FLAG_RELU) v = fmaxf(v, 0.f);
                if (flags & FLAG_HEAD) {
                    int b = n >> 11, s = n & 2047;
                    int h = m >> 6,  dh = m & 63;
                    C[(((size_t)(b * H_ + h)) * S_ + s) * DH_ + dh] = v;
                } else {
                    C[(size_t)n * M + m] = v;
                }
            }
        }
    }
}

// ---------------- flash attention (unchanged, fp32) ----------------
__device__ __forceinline__ float redmax16(float v) {
#pragma unroll
    for (int off = 8; off; off >>= 1) v = fmaxf(v, __shfl_xor_sync(0xffffffffu, v, off, 16));
    return v;
}
__device__ __forceinline__ float redsum16(float v) {
#pragma unroll
    for (int off = 8; off; off >>= 1) v += __shfl_xor_sync(0xffffffffu, v, off, 16);
    return v;
}

#define FA_SMEM (4 * 64 * 68 * 4)

__global__ void flash_attn_kernel(const float* __restrict__ q, const float* __restrict__ k,
                                  const float* __restrict__ v, const int* __restrict__ mask,
                                  float* __restrict__ ctx)
{
    extern __shared__ float sm[];
    float* QsT = sm;                 // [d=64][r=64] pitch 68
    float* KsT = sm + 64 * 68;       // [d][kc]
    float* Vs  = sm + 2 * 64 * 68;   // [key][c]
    float* PsT = sm + 3 * 64 * 68;   // [key][qr]

    const int t = threadIdx.x, tx = t & 15, ty = t >> 4;
    const int bh = blockIdx.y, b = bh >> 4, h = bh & 15;
    const int q0 = blockIdx.x * 64;
    const float* qh = q + (size_t)bh * S_ * DH_;
    const float* kh = k + (size_t)bh * S_ * DH_;
    const float* vh = v + (size_t)bh * S_ * DH_;
    const int* maskb = mask + (size_t)b * S_ * S_;

#pragma unroll
    for (int i = 0; i < 16; i++) {
        int idx = t + i * 256;
        int r = idx >> 6, d = idx & 63;
        QsT[d * 68 + r] = qh[(size_t)(q0 + r) * 64 + d];
    }

    float acc[4][4];
#pragma unroll
    for (int i = 0; i < 4; i++)
#pragma unroll
        for (int j = 0; j < 4; j++) acc[i][j] = 0.f;
    float mrow[4] = {-1e30f, -1e30f, -1e30f, -1e30f};
    float lrow[4] = {0.f, 0.f, 0.f, 0.f};

    for (int k0 = 0; k0 < S_; k0 += 64) {
        __syncthreads();
#pragma unroll
        for (int i = 0; i < 16; i++) {
            int idx = t + i * 256;
            int r = idx >> 6, d = idx & 63;
            float kv = kh[(size_t)(k0 + r) * 64 + d];
            KsT[d * 68 + r] = kv;
            Vs[r * 68 + d]  = vh[(size_t)(k0 + r) * 64 + d];
        }
        __syncthreads();

        float s[4][4];
#pragma unroll
        for (int i = 0; i < 4; i++)
#pragma unroll
            for (int j = 0; j < 4; j++) s[i][j] = 0.f;
        for (int d = 0; d < 64; d++) {
            float4 a = *(const float4*)&QsT[d * 68 + ty * 4];
            float4 bb = *(const float4*)&KsT[d * 68 + tx * 4];
            s[0][0] += a.x * bb.x; s[0][1] += a.x * bb.y; s[0][2] += a.x * bb.z; s[0][3] += a.x * bb.w;
            s[1][0] += a.y * bb.x; s[1][1] += a.y * bb.y; s[1][2] += a.y * bb.z; s[1][3] += a.y * bb.w;
            s[2][0] += a.z * bb.x; s[2][1] += a.z * bb.y; s[2][2] += a.z * bb.z; s[2][3] += a.z * bb.w;
            s[3][0] += a.w * bb.x; s[3][1] += a.w * bb.y; s[3][2] += a.w * bb.z; s[3][3] += a.w * bb.w;
        }

#pragma unroll
        for (int i = 0; i < 4; i++) {
            int qr = q0 + ty * 4 + i;
#pragma unroll
            for (int j = 0; j < 4; j++) {
                float val = s[i][j] * 0.125f;
                int mv = maskb[(size_t)qr * S_ + k0 + tx * 4 + j];
                if (mv == 0) val = -1e9f;
                s[i][j] = val;
            }
        }

#pragma unroll
        for (int i = 0; i < 4; i++) {
            float mx = fmaxf(fmaxf(s[i][0], s[i][1]), fmaxf(s[i][2], s[i][3]));
            mx = redmax16(mx);
            float mnew = fmaxf(mrow[i], mx);
            float corr = __expf(mrow[i] - mnew);
            mrow[i] = mnew;
            float rs = 0.f;
#pragma unroll
            for (int j = 0; j < 4; j++) {
                s[i][j] = __expf(s[i][j] - mnew);
                rs += s[i][j];
            }
            rs = redsum16(rs);
            lrow[i] = lrow[i] * corr + rs;
#pragma unroll
            for (int j = 0; j < 4; j++) acc[i][j] *= corr;
        }

#pragma unroll
        for (int i = 0; i < 4; i++)
#pragma unroll
            for (int j = 0; j < 4; j++)
                PsT[(tx * 4 + j) * 68 + ty * 4 + i] = s[i][j];
        __syncthreads();

        for (int kk = 0; kk < 64; kk++) {
            float4 a = *(const float4*)&PsT[kk * 68 + ty * 4];
            float4 bb = *(const float4*)&Vs[kk * 68 + tx * 4];
            acc[0][0] += a.x * bb.x; acc[0][1] += a.x * bb.y; acc[0][2] += a.x * bb.z; acc[0][3] += a.x * bb.w;
            acc[1][0] += a.y * bb.x; acc[1][1] += a.y * bb.y; acc[1][2] += a.y * bb.z; acc[1][3] += a.y * bb.w;
            acc[2][0] += a.z * bb.x; acc[2][1] += a.z * bb.y; acc[2][2] += a.z * bb.z; acc[2][3] += a.z * bb.w;
            acc[3][0] += a.w * bb.x; acc[3][1] += a.w * bb.y; acc[3][2] += a.w * bb.z; acc[3][3] += a.w * bb.w;
        }
    }

#pragma unroll
    for (int i = 0; i < 4; i++) {
        float inv = 1.f / lrow[i];
        int n = b * S_ + q0 + ty * 4 + i;
#pragma unroll
        for (int j = 0; j < 4; j++) {
            int c = h * 64 + tx * 4 + j;
            ctx[(size_t)n * D_ + c] = acc[i][j] * inv;
        }
    }
}

// ---------------- layer norm (torch semantics: ddof=1, eps on std) ----------------
__global__ void layernorm_kernel(const float* __restrict__ x, const float* __restrict__ alpha,
                                 const float* __restrict__ beta, float* __restrict__ out)
{
    const int row = blockIdx.x;
    const int t = threadIdx.x;               // 256 threads, 4 floats each
    const float4* xr = (const float4*)(x + (size_t)row * D_);
    float4 v = xr[t];
    float sum = v.x + v.y + v.z + v.w;
    float sq  = v.x * v.x + v.y * v.y + v.z * v.z + v.w * v.w;

    __shared__ float ssum[8], ssq[8];
#pragma unroll
    for (int off = 16; off; off >>= 1) {
        sum += __shfl_xor_sync(0xffffffffu, sum, off);
        sq  += __shfl_xor_sync(0xffffffffu, sq, off);
    }
    int warp = t >> 5, lane = t & 31;
    if (lane == 0) { ssum[warp] = sum; ssq[warp] = sq; }
    __syncthreads();
    float tsum = 0.f, tsq = 0.f;
#pragma unroll
    for (int w = 0; w < 8; w++) { tsum += ssum[w]; tsq += ssq[w]; }

    float mean = tsum * (1.f / D_);
    float var  = (tsq - (float)D_ * mean * mean) * (1.f / (D_ - 1));
    float std_ = sqrtf(fmaxf(var, 0.f));
    float inv  = 1.f / (std_ + EPS_);

    const float4* av = (const float4*)alpha;
    const float4* bv = (const float4*)beta;
    float4 a = av[t], bb = bv[t];
    float4 o;
    o.x = a.x * (v.x - mean) * inv + bb.x;
    o.y = a.y * (v.y - mean) * inv + bb.y;
    o.z = a.z * (v.z - mean) * inv + bb.z;
    o.w = a.w * (v.w - mean) * inv + bb.w;
    ((float4*)(out + (size_t)row * D_))[t] = o;
}

// ---------------- launch ----------------
extern "C" void kernel_launch(void* const* d_in, const int* in_sizes, int n_in,
                              void* d_out, int out_size)
{
    const float* src = (const float*)d_in[0];
    const int*   mask = (const int*)d_in[1];
    const float* Wq = (const float*)d_in[2];
    const float* bq = (const float*)d_in[3];
    const float* Wk = (const float*)d_in[4];
    const float* bk = (const float*)d_in[5];
    const float* Wv = (const float*)d_in[6];
    const float* bv = (const float*)d_in[7];
    const float* Wo = (const float*)d_in[8];
    const float* bo = (const float*)d_in[9];
    const float* W1 = (const float*)d_in[10];
    const float* b1 = (const float*)d_in[11];
    const float* W2 = (const float*)d_in[12];
    const float* b2 = (const float*)d_in[13];
    const float* a1 = (const float*)d_in[14];
    const float* be1 = (const float*)d_in[15];
    const float* a2 = (const float*)d_in[16];
    const float* be2 = (const float*)d_in[17];
    float* out = (float*)d_out;

    void *pq, *pk, *pv, *pctx, *px0, *px1, *pff;
    cudaGetSymbolAddress(&pq, g_q);
    cudaGetSymbolAddress(&pk, g_k);
    cudaGetSymbolAddress(&pv, g_v);
    cudaGetSymbolAddress(&pctx, g_ctx);
    cudaGetSymbolAddress(&px0, g_x0);
    cudaGetSymbolAddress(&px1, g_x1);
    cudaGetSymbolAddress(&pff, g_ff);

    cudaFuncSetAttribute(flash_attn_kernel, cudaFuncAttributeMaxDynamicSharedMemorySize, FA_SMEM);

    dim3 blk(256);
    dim3 gD(D_ / 128, N_ / 128);    // (8, 32)
    dim3 gFF(FF_ / 128, N_ / 128);  // (16, 32)

    // QKV projections, stored directly in [B,H,S,Dh] layout
    gemm_tf32<<<gD, blk>>>(src, Wq, bq, nullptr, (float*)pq, N_, D_, D_, FLAG_HEAD);
    gemm_tf32<<<gD, blk>>>(src, Wk, bk, nullptr, (float*)pk, N_, D_, D_, FLAG_HEAD);
    gemm_tf32<<<gD, blk>>>(src, Wv, bv, nullptr, (float*)pv, N_, D_, D_, FLAG_HEAD);

    // attention -> ctx in [N, D] layout
    flash_attn_kernel<<<dim3(S_ / 64, B_ * H_), blk, FA_SMEM>>>(
        (const float*)pq, (const float*)pk, (const float*)pv, mask, (float*)pctx);

    // output projection + residual(src)
    gemm_tf32<<<gD, blk>>>((const float*)pctx, Wo, bo, src, (float*)px0, N_, D_, D_, 0);

    // norm1
    layernorm_kernel<<<N_, blk>>>((const float*)px0, a1, be1, (float*)px1);

    // FFN
    gemm_tf32<<<gFF, blk>>>((const float*)px1, W1, b1, nullptr, (float*)pff, N_, FF_, D_, FLAG_RELU);
    gemm_tf32<<<gD, blk>>>((const float*)pff, W2, b2, (const float*)px1, (float*)px0, N_, D_, FF_, 0);

    // norm2 -> out
    layernorm_kernel<<<N_, blk>>>((const float*)px0, a2, be2, out);
}

// round 5
// speedup vs baseline: 1.4660x; 1.1051x over previous
#include <cuda_runtime.h>
#include <cuda_bf16.h>
#include <cstdint>

#define B_   2
#define S_   2048
#define D_   1024
#define H_   16
#define DH_  64
#define FF_  2048
#define N_   (B_*S_)     // 4096
#define EPS_ 1e-6f

#define FLAG_RELU 1
#define FLAG_HEAD 2

// ---------------- scratch (allocation-free) ----------------
__device__ float g_q[N_ * D_];     // [B,H,S,Dh]
__device__ float g_k[N_ * D_];
__device__ float g_v[N_ * D_];
__device__ float g_ctx[N_ * D_];   // [N, D]
__device__ float g_x0[N_ * D_];
__device__ float g_x1[N_ * D_];
__device__ float g_ff[N_ * FF_];

// ---------------- TF32 helpers ----------------
__device__ __forceinline__ uint32_t f2tf32(float x) {
    uint32_t r;
    asm("cvt.rna.tf32.f32 %0, %1;" : "=r"(r) : "f"(x));
    return r;
}

__device__ __forceinline__ void mma_tf32(float c[4], uint32_t a0, uint32_t a1, uint32_t a2, uint32_t a3,
                                         uint32_t b0, uint32_t b1) {
    asm volatile("mma.sync.aligned.m16n8k8.row.col.f32.tf32.tf32.f32 "
                 "{%0,%1,%2,%3}, {%4,%5,%6,%7}, {%8,%9}, {%0,%1,%2,%3};"
                 : "+f"(c[0]), "+f"(c[1]), "+f"(c[2]), "+f"(c[3])
                 : "r"(a0), "r"(a1), "r"(a2), "r"(a3), "r"(b0), "r"(b1));
}

// fast exp on the FMA pipe (no MUFU): exp(x) = 2^(x*log2e), |rel err| < 3e-6
__device__ __forceinline__ float fast_exp(float x) {
    float y = fmaxf(x * 1.4426950408889634f, -126.0f);
    float t = y + 12582912.0f;                 // 1.5 * 2^23: rounds y to nearest int
    int   n = __float_as_int(t) - 0x4B400000;  // integer part
    float f = y - (t - 12582912.0f);           // frac in [-0.5, 0.5]
    float p = 1.3333558146e-3f;
    p = fmaf(p, f, 9.6181291e-3f);
    p = fmaf(p, f, 5.5504108664e-2f);
    p = fmaf(p, f, 2.4022650696e-1f);
    p = fmaf(p, f, 6.9314718056e-1f);
    p = fmaf(p, f, 1.0f);
    return p * __int_as_float((n + 127) << 23);
}

// ---------------- TF32 tensor-core GEMM (unchanged from passing r4) ----------------
#define PITCH 132

__global__ __launch_bounds__(256)
void gemm_tf32(const float* __restrict__ A, const float* __restrict__ W,
               const float* __restrict__ bias, const float* __restrict__ residual,
               float* __restrict__ C, int N, int M, int K, int flags)
{
    __shared__ uint32_t As[2][16][PITCH];
    __shared__ uint32_t Ws[2][16][PITCH];

    const int t  = threadIdx.x;
    const int w  = t >> 5;
    const int wm = w >> 2;
    const int wn = w & 3;
    const int lane = t & 31;
    const int g  = lane >> 2;
    const int tg = lane & 3;

    const int n0 = blockIdx.y * 128, m0 = blockIdx.x * 128;

    const int lrr = t >> 2;
    const int kq  = t & 3;
    const float* Aptr0 = A + (size_t)(n0 + lrr) * K + kq * 4;
    const float* Aptr1 = A + (size_t)(n0 + lrr + 64) * K + kq * 4;
    const float* Wptr0 = W + (size_t)(m0 + lrr) * K + kq * 4;
    const float* Wptr1 = W + (size_t)(m0 + lrr + 64) * K + kq * 4;

    float acc[4][4][4];
#pragma unroll
    for (int mi = 0; mi < 4; mi++)
#pragma unroll
        for (int ni = 0; ni < 4; ni++)
#pragma unroll
            for (int c = 0; c < 4; c++) acc[mi][ni][c] = 0.f;

    {
        float4 a0 = *(const float4*)Aptr0;
        float4 a1 = *(const float4*)Aptr1;
        float4 w0 = *(const float4*)Wptr0;
        float4 w1 = *(const float4*)Wptr1;
        As[0][kq*4+0][lrr]    = f2tf32(a0.x); As[0][kq*4+1][lrr]    = f2tf32(a0.y);
        As[0][kq*4+2][lrr]    = f2tf32(a0.z); As[0][kq*4+3][lrr]    = f2tf32(a0.w);
        As[0][kq*4+0][lrr+64] = f2tf32(a1.x); As[0][kq*4+1][lrr+64] = f2tf32(a1.y);
        As[0][kq*4+2][lrr+64] = f2tf32(a1.z); As[0][kq*4+3][lrr+64] = f2tf32(a1.w);
        Ws[0][kq*4+0][lrr]    = f2tf32(w0.x); Ws[0][kq*4+1][lrr]    = f2tf32(w0.y);
        Ws[0][kq*4+2][lrr]    = f2tf32(w0.z); Ws[0][kq*4+3][lrr]    = f2tf32(w0.w);
        Ws[0][kq*4+0][lrr+64] = f2tf32(w1.x); Ws[0][kq*4+1][lrr+64] = f2tf32(w1.y);
        Ws[0][kq*4+2][lrr+64] = f2tf32(w1.z); Ws[0][kq*4+3][lrr+64] = f2tf32(w1.w);
    }
    __syncthreads();

    int buf = 0;
    for (int k0 = 16; k0 <= K; k0 += 16) {
        const bool has_next = (k0 < K);
        float4 na0, na1, nw0, nw1;
        if (has_next) {
            na0 = *(const float4*)(Aptr0 + k0);
            na1 = *(const float4*)(Aptr1 + k0);
            nw0 = *(const float4*)(Wptr0 + k0);
            nw1 = *(const float4*)(Wptr1 + k0);
        }

#pragma unroll
        for (int ks = 0; ks < 2; ks++) {
            const int kb = ks * 8;
            uint32_t af[4][4], bf[4][2];
#pragma unroll
            for (int mi = 0; mi < 4; mi++) {
                const int nb = wm * 64 + mi * 16;
                af[mi][0] = As[buf][kb + tg][nb + g];
                af[mi][1] = As[buf][kb + tg][nb + g + 8];
                af[mi][2] = As[buf][kb + tg + 4][nb + g];
                af[mi][3] = As[buf][kb + tg + 4][nb + g + 8];
            }
#pragma unroll
            for (int ni = 0; ni < 4; ni++) {
                const int mb = wn * 32 + ni * 8;
                bf[ni][0] = Ws[buf][kb + tg][mb + g];
                bf[ni][1] = Ws[buf][kb + tg + 4][mb + g];
            }
#pragma unroll
            for (int mi = 0; mi < 4; mi++)
#pragma unroll
                for (int ni = 0; ni < 4; ni++)
                    mma_tf32(acc[mi][ni], af[mi][0], af[mi][1], af[mi][2], af[mi][3],
                             bf[ni][0], bf[ni][1]);
        }

        if (has_next) {
            buf ^= 1;
            As[buf][kq*4+0][lrr]    = f2tf32(na0.x); As[buf][kq*4+1][lrr]    = f2tf32(na0.y);
            As[buf][kq*4+2][lrr]    = f2tf32(na0.z); As[buf][kq*4+3][lrr]    = f2tf32(na0.w);
            As[buf][kq*4+0][lrr+64] = f2tf32(na1.x); As[buf][kq*4+1][lrr+64] = f2tf32(na1.y);
            As[buf][kq*4+2][lrr+64] = f2tf32(na1.z); As[buf][kq*4+3][lrr+64] = f2tf32(na1.w);
            Ws[buf][kq*4+0][lrr]    = f2tf32(nw0.x); Ws[buf][kq*4+1][lrr]    = f2tf32(nw0.y);
            Ws[buf][kq*4+2][lrr]    = f2tf32(nw0.z); Ws[buf][kq*4+3][lrr]    = f2tf32(nw0.w);
            Ws[buf][kq*4+0][lrr+64] = f2tf32(nw1.x); Ws[buf][kq*4+1][lrr+64] = f2tf32(nw1.y);
            Ws[buf][kq*4+2][lrr+64] = f2tf32(nw1.z); Ws[buf][kq*4+3][lrr+64] = f2tf32(nw1.w);
            __syncthreads();
        }
    }

#pragma unroll
    for (int mi = 0; mi < 4; mi++) {
#pragma unroll
        for (int ni = 0; ni < 4; ni++) {
#pragma unroll
            for (int c = 0; c < 4; c++) {
                int n = n0 + wm * 64 + mi * 16 + g + ((c >> 1) ? 8 : 0);
                int m = m0 + wn * 32 + ni * 8 + tg * 2 + (c & 1);
                float v = acc[mi][ni][c] + bias[m];
                if (residual) v += residual[(size_t)n * M + m];
                if (flags & FLAG_RELU) v = fmaxf(v, 0.f);
                if (flags & FLAG_HEAD) {
                    int b = n >> 11, s = n & 2047;
                    int h = m >> 6,  dh = m & 63;
                    C[(((size_t)(b * H_ + h)) * S_ + s) * DH_ + dh] = v;
                } else {
                    C[(size_t)n * M + m] = v;
                }
            }
        }
    }
}

// ---------------- TF32 tensor-core flash attention ----------------
// 64q x 64k tiles, 128 threads (4 warps), each warp owns 16 q-rows.
// Fragments: A(g,tg)/(g+8,tg)/(g,tg+4)/(g+8,tg+4), B(tg,g)/(tg+4,g), C(g,2tg)...
// smem pitch 68 -> fragment LDS bank = 4g+tg (conflict-free).
#define FAP 68
#define FA_SMEM (4 * 64 * FAP * 4)

__global__ __launch_bounds__(128)
void flash_tf32(const float* __restrict__ q, const float* __restrict__ k,
                const float* __restrict__ v, const int* __restrict__ mask,
                float* __restrict__ ctx)
{
    extern __shared__ uint32_t sm4[];
    uint32_t* Qs  = sm4;                 // [q][d]
    uint32_t* Ks  = sm4 + 64 * FAP;      // [kc][d]
    uint32_t* VsT = sm4 + 2 * 64 * FAP;  // [d][kc]  (transposed)
    uint32_t* Ps  = sm4 + 3 * 64 * FAP;  // [q][kc]  (per-warp private rows)

    const int t = threadIdx.x;
    const int w = t >> 5, lane = t & 31;
    const int g = lane >> 2, tg = lane & 3;
    const int qb = w * 16;
    const int bh = blockIdx.y, b = bh >> 4, h = bh & 15;
    const int q0 = blockIdx.x * 64;
    const float* qh = q + (size_t)bh * S_ * DH_;
    const float* kh = k + (size_t)bh * S_ * DH_;
    const float* vh = v + (size_t)bh * S_ * DH_;
    const int* maskb = mask + (size_t)b * S_ * S_;

    // loaders: thread handles row lr = t>>1, columns [lc, lc+32)
    const int lr = t >> 1, lc = (t & 1) * 32;

    {   // Q tile -> smem (tf32)
        const float4* src4 = (const float4*)(qh + (size_t)(q0 + lr) * 64 + lc);
#pragma unroll
        for (int i = 0; i < 8; i++) {
            float4 a = src4[i];
            uint4 u = { f2tf32(a.x), f2tf32(a.y), f2tf32(a.z), f2tf32(a.w) };
            *(uint4*)&Qs[lr * FAP + lc + i * 4] = u;
        }
    }

    float outac[8][4];
#pragma unroll
    for (int j = 0; j < 8; j++)
#pragma unroll
        for (int c = 0; c < 4; c++) outac[j][c] = 0.f;
    float mrow0 = -1e30f, mrow1 = -1e30f;
    float lrow0 = 0.f, lrow1 = 0.f;

    for (int k0 = 0; k0 < S_; k0 += 64) {
        __syncthreads();   // everyone done with prev K/V (and Q visible on iter 0)
        {
            const float4* ks4 = (const float4*)(kh + (size_t)(k0 + lr) * 64 + lc);
            const float4* vs4 = (const float4*)(vh + (size_t)(k0 + lr) * 64 + lc);
#pragma unroll
            for (int i = 0; i < 8; i++) {
                float4 a = ks4[i];
                uint4 u = { f2tf32(a.x), f2tf32(a.y), f2tf32(a.z), f2tf32(a.w) };
                *(uint4*)&Ks[lr * FAP + lc + i * 4] = u;
                float4 bb = vs4[i];
                int d0 = lc + i * 4;
                VsT[(d0 + 0) * FAP + lr] = f2tf32(bb.x);
                VsT[(d0 + 1) * FAP + lr] = f2tf32(bb.y);
                VsT[(d0 + 2) * FAP + lr] = f2tf32(bb.z);
                VsT[(d0 + 3) * FAP + lr] = f2tf32(bb.w);
            }
        }
        __syncthreads();

        // S = Q K^T  (warp: 16 rows x 64 cols = 8 ntiles)
        float sa[8][4];
#pragma unroll
        for (int j = 0; j < 8; j++)
#pragma unroll
            for (int c = 0; c < 4; c++) sa[j][c] = 0.f;
#pragma unroll
        for (int kc = 0; kc < 8; kc++) {
            const int kb = kc * 8;
            uint32_t a0 = Qs[(qb + g) * FAP + kb + tg];
            uint32_t a1 = Qs[(qb + g + 8) * FAP + kb + tg];
            uint32_t a2 = Qs[(qb + g) * FAP + kb + tg + 4];
            uint32_t a3 = Qs[(qb + g + 8) * FAP + kb + tg + 4];
#pragma unroll
            for (int j = 0; j < 8; j++) {
                uint32_t b0 = Ks[(j * 8 + g) * FAP + kb + tg];
                uint32_t b1 = Ks[(j * 8 + g) * FAP + kb + tg + 4];
                mma_tf32(sa[j], a0, a1, a2, a3, b0, b1);
            }
        }

        // scale + mask
        const size_t mrow_a = (size_t)(q0 + qb + g) * S_ + k0;
        const size_t mrow_b = (size_t)(q0 + qb + g + 8) * S_ + k0;
#pragma unroll
        for (int j = 0; j < 8; j++) {
            int col = j * 8 + tg * 2;
            int2 m0 = *(const int2*)&maskb[mrow_a + col];
            int2 m1 = *(const int2*)&maskb[mrow_b + col];
            sa[j][0] = m0.x ? sa[j][0] * 0.125f : -1e9f;
            sa[j][1] = m0.y ? sa[j][1] * 0.125f : -1e9f;
            sa[j][2] = m1.x ? sa[j][2] * 0.125f : -1e9f;
            sa[j][3] = m1.y ? sa[j][3] * 0.125f : -1e9f;
        }

        // row max (rows g and g+8), quad-reduce over tg
        float mx0 = -1e30f, mx1 = -1e30f;
#pragma unroll
        for (int j = 0; j < 8; j++) {
            mx0 = fmaxf(mx0, fmaxf(sa[j][0], sa[j][1]));
            mx1 = fmaxf(mx1, fmaxf(sa[j][2], sa[j][3]));
        }
        mx0 = fmaxf(mx0, __shfl_xor_sync(0xffffffffu, mx0, 1));
        mx0 = fmaxf(mx0, __shfl_xor_sync(0xffffffffu, mx0, 2));
        mx1 = fmaxf(mx1, __shfl_xor_sync(0xffffffffu, mx1, 1));
        mx1 = fmaxf(mx1, __shfl_xor_sync(0xffffffffu, mx1, 2));

        float mn0 = fmaxf(mrow0, mx0), mn1 = fmaxf(mrow1, mx1);
        float cr0 = fast_exp(mrow0 - mn0), cr1 = fast_exp(mrow1 - mn1);
        mrow0 = mn0; mrow1 = mn1;

        float rs0 = 0.f, rs1 = 0.f;
#pragma unroll
        for (int j = 0; j < 8; j++) {
            sa[j][0] = fast_exp(sa[j][0] - mn0);
            sa[j][1] = fast_exp(sa[j][1] - mn0);
            sa[j][2] = fast_exp(sa[j][2] - mn1);
            sa[j][3] = fast_exp(sa[j][3] - mn1);
            rs0 += sa[j][0] + sa[j][1];
            rs1 += sa[j][2] + sa[j][3];
        }
        rs0 += __shfl_xor_sync(0xffffffffu, rs0, 1);
        rs0 += __shfl_xor_sync(0xffffffffu, rs0, 2);
        rs1 += __shfl_xor_sync(0xffffffffu, rs1, 1);
        rs1 += __shfl_xor_sync(0xffffffffu, rs1, 2);
        lrow0 = lrow0 * cr0 + rs0;
        lrow1 = lrow1 * cr1 + rs1;

#pragma unroll
        for (int j = 0; j < 8; j++) {
            outac[j][0] *= cr0; outac[j][1] *= cr0;
            outac[j][2] *= cr1; outac[j][3] *= cr1;
        }

        // P -> smem (tf32), per-warp private rows
#pragma unroll
        for (int j = 0; j < 8; j++) {
            uint2 p0 = { f2tf32(sa[j][0]), f2tf32(sa[j][1]) };
            *(uint2*)&Ps[(qb + g) * FAP + j * 8 + tg * 2] = p0;
            uint2 p1 = { f2tf32(sa[j][2]), f2tf32(sa[j][3]) };
            *(uint2*)&Ps[(qb + g + 8) * FAP + j * 8 + tg * 2] = p1;
        }
        __syncwarp();

        // out += P V   (A = P rows of this warp, B = V^T)
#pragma unroll
        for (int kc = 0; kc < 8; kc++) {
            const int kb = kc * 8;
            uint32_t a0 = Ps[(qb + g) * FAP + kb + tg];
            uint32_t a1 = Ps[(qb + g + 8) * FAP + kb + tg];
            uint32_t a2 = Ps[(qb + g) * FAP + kb + tg + 4];
            uint32_t a3 = Ps[(qb + g + 8) * FAP + kb + tg + 4];
#pragma unroll
            for (int j = 0; j < 8; j++) {
                uint32_t b0 = VsT[(j * 8 + g) * FAP + kb + tg];
                uint32_t b1 = VsT[(j * 8 + g) * FAP + kb + tg + 4];
                mma_tf32(outac[j], a0, a1, a2, a3, b0, b1);
            }
        }
        __syncwarp();  // PV reads done before next-iter P overwrite
    }

    // epilogue
    float i0 = 1.f / lrow0, i1 = 1.f / lrow1;
    const int nrow = b * S_ + q0 + qb + g;
    const int hb = h * 64;
#pragma unroll
    for (int j = 0; j < 8; j++) {
        float2 o0 = { outac[j][0] * i0, outac[j][1] * i0 };
        *(float2*)&ctx[(size_t)nrow * D_ + hb + j * 8 + tg * 2] = o0;
        float2 o1 = { outac[j][2] * i1, outac[j][3] * i1 };
        *(float2*)&ctx[(size_t)(nrow + 8) * D_ + hb + j * 8 + tg * 2] = o1;
    }
}

// ---------------- layer norm (torch semantics: ddof=1, eps on std) ----------------
__global__ void layernorm_kernel(const float* __restrict__ x, const float* __restrict__ alpha,
                                 const float* __restrict__ beta, float* __restrict__ out)
{
    const int row = blockIdx.x;
    const int t = threadIdx.x;
    const float4* xr = (const float4*)(x + (size_t)row * D_);
    float4 v = xr[t];
    float sum = v.x + v.y + v.z + v.w;
    float sq  = v.x * v.x + v.y * v.y + v.z * v.z + v.w * v.w;

    __shared__ float ssum[8], ssq[8];
#pragma unroll
    for (int off = 16; off; off >>= 1) {
        sum += __shfl_xor_sync(0xffffffffu, sum, off);
        sq  += __shfl_xor_sync(0xffffffffu, sq, off);
    }
    int warp = t >> 5, lane = t & 31;
    if (lane == 0) { ssum[warp] = sum; ssq[warp] = sq; }
    __syncthreads();
    float tsum = 0.f, tsq = 0.f;
#pragma unroll
    for (int w = 0; w < 8; w++) { tsum += ssum[w]; tsq += ssq[w]; }

    float mean = tsum * (1.f / D_);
    float var  = (tsq - (float)D_ * mean * mean) * (1.f / (D_ - 1));
    float std_ = sqrtf(fmaxf(var, 0.f));
    float inv  = 1.f / (std_ + EPS_);

    const float4* av = (const float4*)alpha;
    const float4* bv = (const float4*)beta;
    float4 a = av[t], bb = bv[t];
    float4 o;
    o.x = a.x * (v.x - mean) * inv + bb.x;
    o.y = a.y * (v.y - mean) * inv + bb.y;
    o.z = a.z * (v.z - mean) * inv + bb.z;
    o.w = a.w * (v.w - mean) * inv + bb.w;
    ((float4*)(out + (size_t)row * D_))[t] = o;
}

// ---------------- launch ----------------
extern "C" void kernel_launch(void* const* d_in, const int* in_sizes, int n_in,
                              void* d_out, int out_size)
{
    const float* src = (const float*)d_in[0];
    const int*   mask = (const int*)d_in[1];
    const float* Wq = (const float*)d_in[2];
    const float* bq = (const float*)d_in[3];
    const float* Wk = (const float*)d_in[4];
    const float* bk = (const float*)d_in[5];
    const float* Wv = (const float*)d_in[6];
    const float* bv = (const float*)d_in[7];
    const float* Wo = (const float*)d_in[8];
    const float* bo = (const float*)d_in[9];
    const float* W1 = (const float*)d_in[10];
    const float* b1 = (const float*)d_in[11];
    const float* W2 = (const float*)d_in[12];
    const float* b2 = (const float*)d_in[13];
    const float* a1 = (const float*)d_in[14];
    const float* be1 = (const float*)d_in[15];
    const float* a2 = (const float*)d_in[16];
    const float* be2 = (const float*)d_in[17];
    float* out = (float*)d_out;

    void *pq, *pk, *pv, *pctx, *px0, *px1, *pff;
    cudaGetSymbolAddress(&pq, g_q);
    cudaGetSymbolAddress(&pk, g_k);
    cudaGetSymbolAddress(&pv, g_v);
    cudaGetSymbolAddress(&pctx, g_ctx);
    cudaGetSymbolAddress(&px0, g_x0);
    cudaGetSymbolAddress(&px1, g_x1);
    cudaGetSymbolAddress(&pff, g_ff);

    cudaFuncSetAttribute(flash_tf32, cudaFuncAttributeMaxDynamicSharedMemorySize, FA_SMEM);

    dim3 blk(256);
    dim3 gD(D_ / 128, N_ / 128);    // (8, 32)
    dim3 gFF(FF_ / 128, N_ / 128);  // (16, 32)

    // QKV projections, stored directly in [B,H,S,Dh] layout
    gemm_tf32<<<gD, blk>>>(src, Wq, bq, nullptr, (float*)pq, N_, D_, D_, FLAG_HEAD);
    gemm_tf32<<<gD, blk>>>(src, Wk, bk, nullptr, (float*)pk, N_, D_, D_, FLAG_HEAD);
    gemm_tf32<<<gD, blk>>>(src, Wv, bv, nullptr, (float*)pv, N_, D_, D_, FLAG_HEAD);

    // attention -> ctx in [N, D] layout (tensor-core flash)
    flash_tf32<<<dim3(S_ / 64, B_ * H_), dim3(128), FA_SMEM>>>(
        (const float*)pq, (const float*)pk, (const float*)pv, mask, (float*)pctx);

    // output projection + residual(src)
    gemm_tf32<<<gD, blk>>>((const float*)pctx, Wo, bo, src, (float*)px0, N_, D_, D_, 0);

    // norm1
    layernorm_kernel<<<N_, blk>>>((const float*)px0, a1, be1, (float*)px1);

    // FFN
    gemm_tf32<<<gFF, blk>>>((const float*)px1, W1, b1, nullptr, (float*)pff, N_, FF_, D_, FLAG_RELU);
    gemm_tf32<<<gD, blk>>>((const float*)pff, W2, b2, (const float*)px1, (float*)px0, N_, D_, FF_, 0);

    // norm2 -> out
    layernorm_kernel<<<N_, blk>>>((const float*)px0, a2, be2, out);
}

// round 6
// speedup vs baseline: 1.8538x; 1.2645x over previous
#include <cuda_runtime.h>
#include <cuda_bf16.h>
#include <cstdint>

#define B_   2
#define S_   2048
#define D_   1024
#define H_   16
#define DH_  64
#define FF_  2048
#define N_   (B_*S_)     // 4096
#define EPS_ 1e-6f

#define FLAG_RELU 1
#define FLAG_HEAD 2

// ---------------- scratch (allocation-free) ----------------
__device__ float g_q[N_ * D_];     // [B,H,S,Dh]
__device__ float g_k[N_ * D_];
__device__ float g_v[N_ * D_];
__device__ float g_ctx[N_ * D_];   // [N, D]
__device__ float g_x0[N_ * D_];
__device__ float g_x1[N_ * D_];
__device__ float g_ff[N_ * FF_];

// ---------------- TF32 helpers ----------------
__device__ __forceinline__ uint32_t f2tf32(float x) {
    uint32_t r;
    asm("cvt.rna.tf32.f32 %0, %1;" : "=r"(r) : "f"(x));
    return r;
}

__device__ __forceinline__ void mma_tf32(float c[4], uint32_t a0, uint32_t a1, uint32_t a2, uint32_t a3,
                                         uint32_t b0, uint32_t b1) {
    asm volatile("mma.sync.aligned.m16n8k8.row.col.f32.tf32.tf32.f32 "
                 "{%0,%1,%2,%3}, {%4,%5,%6,%7}, {%8,%9}, {%0,%1,%2,%3};"
                 : "+f"(c[0]), "+f"(c[1]), "+f"(c[2]), "+f"(c[3])
                 : "r"(a0), "r"(a1), "r"(a2), "r"(a3), "r"(b0), "r"(b1));
}

// fast exp on the FMA pipe (no MUFU): exp(x) = 2^(x*log2e), |rel err| < 3e-6
__device__ __forceinline__ float fast_exp(float x) {
    float y = fmaxf(x * 1.4426950408889634f, -126.0f);
    float t = y + 12582912.0f;                 // 1.5 * 2^23: rounds y to nearest int
    int   n = __float_as_int(t) - 0x4B400000;  // integer part
    float f = y - (t - 12582912.0f);           // frac in [-0.5, 0.5]
    float p = 1.3333558146e-3f;
    p = fmaf(p, f, 9.6181291e-3f);
    p = fmaf(p, f, 5.5504108664e-2f);
    p = fmaf(p, f, 2.4022650696e-1f);
    p = fmaf(p, f, 6.9314718056e-1f);
    p = fmaf(p, f, 1.0f);
    return p * __int_as_float((n + 127) << 23);
}

// ---------------- TF32 tensor-core GEMM (unchanged) ----------------
#define PITCH 132

__global__ __launch_bounds__(256)
void gemm_tf32(const float* __restrict__ A, const float* __restrict__ W,
               const float* __restrict__ bias, const float* __restrict__ residual,
               float* __restrict__ C, int N, int M, int K, int flags)
{
    __shared__ uint32_t As[2][16][PITCH];
    __shared__ uint32_t Ws[2][16][PITCH];

    const int t  = threadIdx.x;
    const int w  = t >> 5;
    const int wm = w >> 2;
    const int wn = w & 3;
    const int lane = t & 31;
    const int g  = lane >> 2;
    const int tg = lane & 3;

    const int n0 = blockIdx.y * 128, m0 = blockIdx.x * 128;

    const int lrr = t >> 2;
    const int kq  = t & 3;
    const float* Aptr0 = A + (size_t)(n0 + lrr) * K + kq * 4;
    const float* Aptr1 = A + (size_t)(n0 + lrr + 64) * K + kq * 4;
    const float* Wptr0 = W + (size_t)(m0 + lrr) * K + kq * 4;
    const float* Wptr1 = W + (size_t)(m0 + lrr + 64) * K + kq * 4;

    float acc[4][4][4];
#pragma unroll
    for (int mi = 0; mi < 4; mi++)
#pragma unroll
        for (int ni = 0; ni < 4; ni++)
#pragma unroll
            for (int c = 0; c < 4; c++) acc[mi][ni][c] = 0.f;

    {
        float4 a0 = *(const float4*)Aptr0;
        float4 a1 = *(const float4*)Aptr1;
        float4 w0 = *(const float4*)Wptr0;
        float4 w1 = *(const float4*)Wptr1;
        As[0][kq*4+0][lrr]    = f2tf32(a0.x); As[0][kq*4+1][lrr]    = f2tf32(a0.y);
        As[0][kq*4+2][lrr]    = f2tf32(a0.z); As[0][kq*4+3][lrr]    = f2tf32(a0.w);
        As[0][kq*4+0][lrr+64] = f2tf32(a1.x); As[0][kq*4+1][lrr+64] = f2tf32(a1.y);
        As[0][kq*4+2][lrr+64] = f2tf32(a1.z); As[0][kq*4+3][lrr+64] = f2tf32(a1.w);
        Ws[0][kq*4+0][lrr]    = f2tf32(w0.x); Ws[0][kq*4+1][lrr]    = f2tf32(w0.y);
        Ws[0][kq*4+2][lrr]    = f2tf32(w0.z); Ws[0][kq*4+3][lrr]    = f2tf32(w0.w);
        Ws[0][kq*4+0][lrr+64] = f2tf32(w1.x); Ws[0][kq*4+1][lrr+64] = f2tf32(w1.y);
        Ws[0][kq*4+2][lrr+64] = f2tf32(w1.z); Ws[0][kq*4+3][lrr+64] = f2tf32(w1.w);
    }
    __syncthreads();

    int buf = 0;
    for (int k0 = 16; k0 <= K; k0 += 16) {
        const bool has_next = (k0 < K);
        float4 na0, na1, nw0, nw1;
        if (has_next) {
            na0 = *(const float4*)(Aptr0 + k0);
            na1 = *(const float4*)(Aptr1 + k0);
            nw0 = *(const float4*)(Wptr0 + k0);
            nw1 = *(const float4*)(Wptr1 + k0);
        }

#pragma unroll
        for (int ks = 0; ks < 2; ks++) {
            const int kb = ks * 8;
            uint32_t af[4][4], bf[4][2];
#pragma unroll
            for (int mi = 0; mi < 4; mi++) {
                const int nb = wm * 64 + mi * 16;
                af[mi][0] = As[buf][kb + tg][nb + g];
                af[mi][1] = As[buf][kb + tg][nb + g + 8];
                af[mi][2] = As[buf][kb + tg + 4][nb + g];
                af[mi][3] = As[buf][kb + tg + 4][nb + g + 8];
            }
#pragma unroll
            for (int ni = 0; ni < 4; ni++) {
                const int mb = wn * 32 + ni * 8;
                bf[ni][0] = Ws[buf][kb + tg][mb + g];
                bf[ni][1] = Ws[buf][kb + tg + 4][mb + g];
            }
#pragma unroll
            for (int mi = 0; mi < 4; mi++)
#pragma unroll
                for (int ni = 0; ni < 4; ni++)
                    mma_tf32(acc[mi][ni], af[mi][0], af[mi][1], af[mi][2], af[mi][3],
                             bf[ni][0], bf[ni][1]);
        }

        if (has_next) {
            buf ^= 1;
            As[buf][kq*4+0][lrr]    = f2tf32(na0.x); As[buf][kq*4+1][lrr]    = f2tf32(na0.y);
            As[buf][kq*4+2][lrr]    = f2tf32(na0.z); As[buf][kq*4+3][lrr]    = f2tf32(na0.w);
            As[buf][kq*4+0][lrr+64] = f2tf32(na1.x); As[buf][kq*4+1][lrr+64] = f2tf32(na1.y);
            As[buf][kq*4+2][lrr+64] = f2tf32(na1.z); As[buf][kq*4+3][lrr+64] = f2tf32(na1.w);
            Ws[buf][kq*4+0][lrr]    = f2tf32(nw0.x); Ws[buf][kq*4+1][lrr]    = f2tf32(nw0.y);
            Ws[buf][kq*4+2][lrr]    = f2tf32(nw0.z); Ws[buf][kq*4+3][lrr]    = f2tf32(nw0.w);
            Ws[buf][kq*4+0][lrr+64] = f2tf32(nw1.x); Ws[buf][kq*4+1][lrr+64] = f2tf32(nw1.y);
            Ws[buf][kq*4+2][lrr+64] = f2tf32(nw1.z); Ws[buf][kq*4+3][lrr+64] = f2tf32(nw1.w);
            __syncthreads();
        }
    }

#pragma unroll
    for (int mi = 0; mi < 4; mi++) {
#pragma unroll
        for (int ni = 0; ni < 4; ni++) {
#pragma unroll
            for (int c = 0; c < 4; c++) {
                int n = n0 + wm * 64 + mi * 16 + g + ((c >> 1) ? 8 : 0);
                int m = m0 + wn * 32 + ni * 8 + tg * 2 + (c & 1);
                float v = acc[mi][ni][c] + bias[m];
                if (residual) v += residual[(size_t)n * M + m];
                if (flags & FLAG_RELU) v = fmaxf(v, 0.f);
                if (flags & FLAG_HEAD) {
                    int b = n >> 11, s = n & 2047;
                    int h = m >> 6,  dh = m & 63;
                    C[(((size_t)(b * H_ + h)) * S_ + s) * DH_ + dh] = v;
                } else {
                    C[(size_t)n * M + m] = v;
                }
            }
        }
    }
}

// ---------------- TF32 tensor-core flash attention ----------------
// CTA: 128 q-rows x 64 k per step, 256 threads (8 warps), warp w owns rows 16w..16w+15.
// Fragments: A(g,tg)/(g+8,tg)/(g,tg+4)/(g+8,tg+4), B(tg,g)/(tg+4,g), C(g,2tg)...
// smem pitch 68 -> fragment LDS bank = 4g+tg (conflict-free).
#define FAP 68
#define FA_SMEM ((128 + 64 + 64 + 128) * FAP * 4)

__global__ __launch_bounds__(256, 2)
void flash_tf32(const float* __restrict__ q, const float* __restrict__ k,
                const float* __restrict__ v, const int* __restrict__ mask,
                float* __restrict__ ctx)
{
    extern __shared__ uint32_t sm4[];
    uint32_t* Qs  = sm4;                  // [128 q][d]
    uint32_t* Ks  = sm4 + 128 * FAP;      // [64 kc][d]
    uint32_t* VsT = sm4 + 192 * FAP;      // [d][64 kc]  (transposed)
    uint32_t* Ps  = sm4 + 256 * FAP;      // [128 q][kc] (per-warp private rows)

    const int t = threadIdx.x;
    const int w = t >> 5, lane = t & 31;
    const int g = lane >> 2, tg = lane & 3;
    const int qb = w * 16;
    const int bh = blockIdx.y, b = bh >> 4, h = bh & 15;
    const int q0 = blockIdx.x * 128;
    const float* qh = q + (size_t)bh * S_ * DH_;
    const float* kh = k + (size_t)bh * S_ * DH_;
    const float* vh = v + (size_t)bh * S_ * DH_;
    const int* maskb = mask + (size_t)b * S_ * S_;

    {   // Q tile (128x64) -> smem (tf32): row = t>>1, cols [ (t&1)*32, +32 )
        const int lr = t >> 1, lc = (t & 1) * 32;
        const float4* src4 = (const float4*)(qh + (size_t)(q0 + lr) * 64 + lc);
#pragma unroll
        for (int i = 0; i < 8; i++) {
            float4 a = src4[i];
            uint4 u = { f2tf32(a.x), f2tf32(a.y), f2tf32(a.z), f2tf32(a.w) };
            *(uint4*)&Qs[lr * FAP + lc + i * 4] = u;
        }
    }

    // K/V loader mapping: 64 rows, 4 threads/row, each 16 cols
    const int krow = t & 63;
    const int kcol = (t >> 6) * 16;

    float outac[8][4];
#pragma unroll
    for (int j = 0; j < 8; j++)
#pragma unroll
        for (int c = 0; c < 4; c++) outac[j][c] = 0.f;
    float mrow0 = -1e30f, mrow1 = -1e30f;
    float lrow0 = 0.f, lrow1 = 0.f;

    for (int k0 = 0; k0 < S_; k0 += 64) {
        __syncthreads();   // everyone done with prev K/V (and Q visible on iter 0)
        {
            const float4* ks4 = (const float4*)(kh + (size_t)(k0 + krow) * 64 + kcol);
            const float4* vs4 = (const float4*)(vh + (size_t)(k0 + krow) * 64 + kcol);
#pragma unroll
            for (int i = 0; i < 4; i++) {
                float4 a = ks4[i];
                uint4 u = { f2tf32(a.x), f2tf32(a.y), f2tf32(a.z), f2tf32(a.w) };
                *(uint4*)&Ks[krow * FAP + kcol + i * 4] = u;
                float4 bb = vs4[i];
                int d0 = kcol + i * 4;
                VsT[(d0 + 0) * FAP + krow] = f2tf32(bb.x);
                VsT[(d0 + 1) * FAP + krow] = f2tf32(bb.y);
                VsT[(d0 + 2) * FAP + krow] = f2tf32(bb.z);
                VsT[(d0 + 3) * FAP + krow] = f2tf32(bb.w);
            }
        }
        __syncthreads();

        // S = Q K^T  (warp: 16 rows x 64 cols = 8 ntiles)
        float sa[8][4];
#pragma unroll
        for (int j = 0; j < 8; j++)
#pragma unroll
            for (int c = 0; c < 4; c++) sa[j][c] = 0.f;
#pragma unroll
        for (int kc = 0; kc < 8; kc++) {
            const int kb = kc * 8;
            uint32_t a0 = Qs[(qb + g) * FAP + kb + tg];
            uint32_t a1 = Qs[(qb + g + 8) * FAP + kb + tg];
            uint32_t a2 = Qs[(qb + g) * FAP + kb + tg + 4];
            uint32_t a3 = Qs[(qb + g + 8) * FAP + kb + tg + 4];
#pragma unroll
            for (int j = 0; j < 8; j++) {
                uint32_t b0 = Ks[(j * 8 + g) * FAP + kb + tg];
                uint32_t b1 = Ks[(j * 8 + g) * FAP + kb + tg + 4];
                mma_tf32(sa[j], a0, a1, a2, a3, b0, b1);
            }
        }

        // scale + mask
        const size_t mrow_a = (size_t)(q0 + qb + g) * S_ + k0;
        const size_t mrow_b = (size_t)(q0 + qb + g + 8) * S_ + k0;
#pragma unroll
        for (int j = 0; j < 8; j++) {
            int col = j * 8 + tg * 2;
            int2 m0 = *(const int2*)&maskb[mrow_a + col];
            int2 m1 = *(const int2*)&maskb[mrow_b + col];
            sa[j][0] = m0.x ? sa[j][0] * 0.125f : -1e9f;
            sa[j][1] = m0.y ? sa[j][1] * 0.125f : -1e9f;
            sa[j][2] = m1.x ? sa[j][2] * 0.125f : -1e9f;
            sa[j][3] = m1.y ? sa[j][3] * 0.125f : -1e9f;
        }

        // row max (rows g and g+8), quad-reduce over tg
        float mx0 = -1e30f, mx1 = -1e30f;
#pragma unroll
        for (int j = 0; j < 8; j++) {
            mx0 = fmaxf(mx0, fmaxf(sa[j][0], sa[j][1]));
            mx1 = fmaxf(mx1, fmaxf(sa[j][2], sa[j][3]));
        }
        mx0 = fmaxf(mx0, __shfl_xor_sync(0xffffffffu, mx0, 1));
        mx0 = fmaxf(mx0, __shfl_xor_sync(0xffffffffu, mx0, 2));
        mx1 = fmaxf(mx1, __shfl_xor_sync(0xffffffffu, mx1, 1));
        mx1 = fmaxf(mx1, __shfl_xor_sync(0xffffffffu, mx1, 2));

        float mn0 = fmaxf(mrow0, mx0), mn1 = fmaxf(mrow1, mx1);
        float cr0 = fast_exp(mrow0 - mn0), cr1 = fast_exp(mrow1 - mn1);
        mrow0 = mn0; mrow1 = mn1;

        float rs0 = 0.f, rs1 = 0.f;
#pragma unroll
        for (int j = 0; j < 8; j++) {
            sa[j][0] = fast_exp(sa[j][0] - mn0);
            sa[j][1] = fast_exp(sa[j][1] - mn0);
            sa[j][2] = fast_exp(sa[j][2] - mn1);
            sa[j][3] = fast_exp(sa[j][3] - mn1);
            rs0 += sa[j][0] + sa[j][1];
            rs1 += sa[j][2] + sa[j][3];
        }
        rs0 += __shfl_xor_sync(0xffffffffu, rs0, 1);
        rs0 += __shfl_xor_sync(0xffffffffu, rs0, 2);
        rs1 += __shfl_xor_sync(0xffffffffu, rs1, 1);
        rs1 += __shfl_xor_sync(0xffffffffu, rs1, 2);
        lrow0 = lrow0 * cr0 + rs0;
        lrow1 = lrow1 * cr1 + rs1;

#pragma unroll
        for (int j = 0; j < 8; j++) {
            outac[j][0] *= cr0; outac[j][1] *= cr0;
            outac[j][2] *= cr1; outac[j][3] *= cr1;
        }

        // P -> smem (tf32), per-warp private rows
#pragma unroll
        for (int j = 0; j < 8; j++) {
            uint2 p0 = { f2tf32(sa[j][0]), f2tf32(sa[j][1]) };
            *(uint2*)&Ps[(qb + g) * FAP + j * 8 + tg * 2] = p0;
            uint2 p1 = { f2tf32(sa[j][2]), f2tf32(sa[j][3]) };
            *(uint2*)&Ps[(qb + g + 8) * FAP + j * 8 + tg * 2] = p1;
        }
        __syncwarp();

        // out += P V   (A = P rows of this warp, B = V^T)
#pragma unroll
        for (int kc = 0; kc < 8; kc++) {
            const int kb = kc * 8;
            uint32_t a0 = Ps[(qb + g) * FAP + kb + tg];
            uint32_t a1 = Ps[(qb + g + 8) * FAP + kb + tg];
            uint32_t a2 = Ps[(qb + g) * FAP + kb + tg + 4];
            uint32_t a3 = Ps[(qb + g + 8) * FAP + kb + tg + 4];
#pragma unroll
            for (int j = 0; j < 8; j++) {
                uint32_t b0 = VsT[(j * 8 + g) * FAP + kb + tg];
                uint32_t b1 = VsT[(j * 8 + g) * FAP + kb + tg + 4];
                mma_tf32(outac[j], a0, a1, a2, a3, b0, b1);
            }
        }
        __syncwarp();  // PV reads done before next-iter P overwrite
    }

    // epilogue
    float i0 = 1.f / lrow0, i1 = 1.f / lrow1;
    const int nrow = b * S_ + q0 + qb + g;
    const int hb = h * 64;
#pragma unroll
    for (int j = 0; j < 8; j++) {
        float2 o0 = { outac[j][0] * i0, outac[j][1] * i0 };
        *(float2*)&ctx[(size_t)nrow * D_ + hb + j * 8 + tg * 2] = o0;
        float2 o1 = { outac[j][2] * i1, outac[j][3] * i1 };
        *(float2*)&ctx[(size_t)(nrow + 8) * D_ + hb + j * 8 + tg * 2] = o1;
    }
}

// ---------------- layer norm (torch semantics: ddof=1, eps on std) ----------------
__global__ void layernorm_kernel(const float* __restrict__ x, const float* __restrict__ alpha,
                                 const float* __restrict__ beta, float* __restrict__ out)
{
    const int row = blockIdx.x;
    const int t = threadIdx.x;
    const float4* xr = (const float4*)(x + (size_t)row * D_);
    float4 v = xr[t];
    float sum = v.x + v.y + v.z + v.w;
    float sq  = v.x * v.x + v.y * v.y + v.z * v.z + v.w * v.w;

    __shared__ float ssum[8], ssq[8];
#pragma unroll
    for (int off = 16; off; off >>= 1) {
        sum += __shfl_xor_sync(0xffffffffu, sum, off);
        sq  += __shfl_xor_sync(0xffffffffu, sq, off);
    }
    int warp = t >> 5, lane = t & 31;
    if (lane == 0) { ssum[warp] = sum; ssq[warp] = sq; }
    __syncthreads();
    float tsum = 0.f, tsq = 0.f;
#pragma unroll
    for (int w = 0; w < 8; w++) { tsum += ssum[w]; tsq += ssq[w]; }

    float mean = tsum * (1.f / D_);
    float var  = (tsq - (float)D_ * mean * mean) * (1.f / (D_ - 1));
    float std_ = sqrtf(fmaxf(var, 0.f));
    float inv  = 1.f / (std_ + EPS_);

    const float4* av = (const float4*)alpha;
    const float4* bv = (const float4*)beta;
    float4 a = av[t], bb = bv[t];
    float4 o;
    o.x = a.x * (v.x - mean) * inv + bb.x;
    o.y = a.y * (v.y - mean) * inv + bb.y;
    o.z = a.z * (v.z - mean) * inv + bb.z;
    o.w = a.w * (v.w - mean) * inv + bb.w;
    ((float4*)(out + (size_t)row * D_))[t] = o;
}

// ---------------- launch ----------------
extern "C" void kernel_launch(void* const* d_in, const int* in_sizes, int n_in,
                              void* d_out, int out_size)
{
    const float* src = (const float*)d_in[0];
    const int*   mask = (const int*)d_in[1];
    const float* Wq = (const float*)d_in[2];
    const float* bq = (const float*)d_in[3];
    const float* Wk = (const float*)d_in[4];
    const float* bk = (const float*)d_in[5];
    const float* Wv = (const float*)d_in[6];
    const float* bv = (const float*)d_in[7];
    const float* Wo = (const float*)d_in[8];
    const float* bo = (const float*)d_in[9];
    const float* W1 = (const float*)d_in[10];
    const float* b1 = (const float*)d_in[11];
    const float* W2 = (const float*)d_in[12];
    const float* b2 = (const float*)d_in[13];
    const float* a1 = (const float*)d_in[14];
    const float* be1 = (const float*)d_in[15];
    const float* a2 = (const float*)d_in[16];
    const float* be2 = (const float*)d_in[17];
    float* out = (float*)d_out;

    void *pq, *pk, *pv, *pctx, *px0, *px1, *pff;
    cudaGetSymbolAddress(&pq, g_q);
    cudaGetSymbolAddress(&pk, g_k);
    cudaGetSymbolAddress(&pv, g_v);
    cudaGetSymbolAddress(&pctx, g_ctx);
    cudaGetSymbolAddress(&px0, g_x0);
    cudaGetSymbolAddress(&px1, g_x1);
    cudaGetSymbolAddress(&pff, g_ff);

    cudaFuncSetAttribute(flash_tf32, cudaFuncAttributeMaxDynamicSharedMemorySize, FA_SMEM);

    dim3 blk(256);
    dim3 gD(D_ / 128, N_ / 128);    // (8, 32)
    dim3 gFF(FF_ / 128, N_ / 128);  // (16, 32)

    // QKV projections, stored directly in [B,H,S,Dh] layout
    gemm_tf32<<<gD, blk>>>(src, Wq, bq, nullptr, (float*)pq, N_, D_, D_, FLAG_HEAD);
    gemm_tf32<<<gD, blk>>>(src, Wk, bk, nullptr, (float*)pk, N_, D_, D_, FLAG_HEAD);
    gemm_tf32<<<gD, blk>>>(src, Wv, bv, nullptr, (float*)pv, N_, D_, D_, FLAG_HEAD);

    // attention -> ctx in [N, D] layout (tensor-core flash, 128q CTA)
    flash_tf32<<<dim3(S_ / 128, B_ * H_), dim3(256), FA_SMEM>>>(
        (const float*)pq, (const float*)pk, (const float*)pv, mask, (float*)pctx);

    // output projection + residual(src)
    gemm_tf32<<<gD, blk>>>((const float*)pctx, Wo, bo, src, (float*)px0, N_, D_, D_, 0);

    // norm1
    layernorm_kernel<<<N_, blk>>>((const float*)px0, a1, be1, (float*)px1);

    // FFN
    gemm_tf32<<<gFF, blk>>>((const float*)px1, W1, b1, nullptr, (float*)pff, N_, FF_, D_, FLAG_RELU);
    gemm_tf32<<<gD, blk>>>((const float*)pff, W2, b2, (const float*)px1, (float*)px0, N_, D_, FF_, 0);

    // norm2 -> out
    layernorm_kernel<<<N_, blk>>>((const float*)px0, a2, be2, out);
}

// round 7
// speedup vs baseline: 2.5415x; 1.3710x over previous
#include <cuda_runtime.h>
#include <cuda_bf16.h>
#include <cstdint>

#define B_   2
#define S_   2048
#define D_   1024
#define H_   16
#define DH_  64
#define FF_  2048
#define N_   (B_*S_)     // 4096
#define EPS_ 1e-6f

#define FLAG_RELU 1
#define FLAG_HEAD 2

// ---------------- scratch (allocation-free) ----------------
__device__ float g_q[N_ * D_];     // [B,H,S,Dh]
__device__ float g_k[N_ * D_];
__device__ float g_v[N_ * D_];
__device__ float g_ctx[N_ * D_];   // [N, D]
__device__ float g_x0[N_ * D_];
__device__ float g_x1[N_ * D_];
__device__ float g_ff[N_ * FF_];

// ---------------- helpers ----------------
__device__ __forceinline__ uint32_t f2tf32(float x) {
    uint32_t r;
    asm("cvt.rna.tf32.f32 %0, %1;" : "=r"(r) : "f"(x));
    return r;
}

__device__ __forceinline__ uint32_t pack_bf16(float lo, float hi) {
    uint32_t r;
    asm("cvt.rn.bf16x2.f32 %0, %1, %2;" : "=r"(r) : "f"(hi), "f"(lo));
    return r;
}

__device__ __forceinline__ void mma_tf32(float c[4], uint32_t a0, uint32_t a1, uint32_t a2, uint32_t a3,
                                         uint32_t b0, uint32_t b1) {
    asm volatile("mma.sync.aligned.m16n8k8.row.col.f32.tf32.tf32.f32 "
                 "{%0,%1,%2,%3}, {%4,%5,%6,%7}, {%8,%9}, {%0,%1,%2,%3};"
                 : "+f"(c[0]), "+f"(c[1]), "+f"(c[2]), "+f"(c[3])
                 : "r"(a0), "r"(a1), "r"(a2), "r"(a3), "r"(b0), "r"(b1));
}

__device__ __forceinline__ void mma_bf16(float c[4], uint32_t a0, uint32_t a1, uint32_t a2, uint32_t a3,
                                         uint32_t b0, uint32_t b1) {
    asm volatile("mma.sync.aligned.m16n8k16.row.col.f32.bf16.bf16.f32 "
                 "{%0,%1,%2,%3}, {%4,%5,%6,%7}, {%8,%9}, {%0,%1,%2,%3};"
                 : "+f"(c[0]), "+f"(c[1]), "+f"(c[2]), "+f"(c[3])
                 : "r"(a0), "r"(a1), "r"(a2), "r"(a3), "r"(b0), "r"(b1));
}

__device__ __forceinline__ void cp_async16(uint32_t dst, const void* src) {
    asm volatile("cp.async.cg.shared.global [%0], [%1], 16;" :: "r"(dst), "l"(src));
}
__device__ __forceinline__ void cp_commit() { asm volatile("cp.async.commit_group;" ::: "memory"); }
__device__ __forceinline__ void cp_wait1()  { asm volatile("cp.async.wait_group 1;" ::: "memory"); }

// fast exp on the FMA pipe (no MUFU)
__device__ __forceinline__ float fast_exp(float x) {
    float y = fmaxf(x * 1.4426950408889634f, -126.0f);
    float t = y + 12582912.0f;
    int   n = __float_as_int(t) - 0x4B400000;
    float f = y - (t - 12582912.0f);
    float p = 1.3333558146e-3f;
    p = fmaf(p, f, 9.6181291e-3f);
    p = fmaf(p, f, 5.5504108664e-2f);
    p = fmaf(p, f, 2.4022650696e-1f);
    p = fmaf(p, f, 6.9314718056e-1f);
    p = fmaf(p, f, 1.0f);
    return p * __int_as_float((n + 127) << 23);
}

// ---------------- TF32 GEMM: cp.async 3-stage pipeline ----------------
// Layout: [row][k] pitch GPITCH floats. Fragment bank = (20g+tg) mod 32 -> distinct.
// Raw f32 in smem; HMMA.TF32 truncates mantissa in HW (cutlass f32 path).
#define GPITCH 20
#define GSTAGES 3
#define GSTAGE_U32 (128 * GPITCH)
#define GEMM_SMEM (GSTAGES * 2 * GSTAGE_U32 * 4)   // 61440 B

__global__ __launch_bounds__(256, 2)
void gemm_tf32(const float* __restrict__ A, const float* __restrict__ W,
               const float* __restrict__ bias, const float* __restrict__ residual,
               float* __restrict__ C, int N, int M, int K, int flags)
{
    extern __shared__ uint32_t gsm[];
    uint32_t* Asm = gsm;                               // [st][128][GPITCH]
    uint32_t* Wsm = gsm + GSTAGES * GSTAGE_U32;

    const int t  = threadIdx.x;
    const int w  = t >> 5;
    const int wm = w >> 2;           // 0..1
    const int wn = w & 3;            // 0..3
    const int lane = t & 31;
    const int g  = lane >> 2;
    const int tg = lane & 3;

    const int n0 = blockIdx.y * 128, m0 = blockIdx.x * 128;

    const int lrr = t >> 2;          // 0..63
    const int kq  = t & 3;
    const float* Aptr0 = A + (size_t)(n0 + lrr) * K + kq * 4;
    const float* Aptr1 = A + (size_t)(n0 + lrr + 64) * K + kq * 4;
    const float* Wptr0 = W + (size_t)(m0 + lrr) * K + kq * 4;
    const float* Wptr1 = W + (size_t)(m0 + lrr + 64) * K + kq * 4;

    const uint32_t aBase = (uint32_t)__cvta_generic_to_shared(Asm);
    const uint32_t wBase = (uint32_t)__cvta_generic_to_shared(Wsm);
    const uint32_t off0 = (lrr * GPITCH + kq * 4) * 4;
    const uint32_t off1 = ((lrr + 64) * GPITCH + kq * 4) * 4;

    const int KT = K >> 4;

    // prologue: stages 0,1
#pragma unroll
    for (int st = 0; st < GSTAGES - 1; st++) {
        const uint32_t sb = st * GSTAGE_U32 * 4;
        const int k0 = st * 16;
        cp_async16(aBase + sb + off0, Aptr0 + k0);
        cp_async16(aBase + sb + off1, Aptr1 + k0);
        cp_async16(wBase + sb + off0, Wptr0 + k0);
        cp_async16(wBase + sb + off1, Wptr1 + k0);
        cp_commit();
    }

    float acc[4][4][4];
#pragma unroll
    for (int mi = 0; mi < 4; mi++)
#pragma unroll
        for (int ni = 0; ni < 4; ni++)
#pragma unroll
            for (int c = 0; c < 4; c++) acc[mi][ni][c] = 0.f;

    for (int kt = 0; kt < KT; kt++) {
        cp_wait1();
        __syncthreads();
        const uint32_t* As_ = Asm + (kt % GSTAGES) * GSTAGE_U32;
        const uint32_t* Ws_ = Wsm + (kt % GSTAGES) * GSTAGE_U32;

#pragma unroll
        for (int ks = 0; ks < 2; ks++) {
            const int kb = ks * 8;
            uint32_t af[4][4], bf[4][2];
#pragma unroll
            for (int mi = 0; mi < 4; mi++) {
                const int nb = wm * 64 + mi * 16;
                af[mi][0] = As_[(nb + g) * GPITCH + kb + tg];
                af[mi][1] = As_[(nb + g + 8) * GPITCH + kb + tg];
                af[mi][2] = As_[(nb + g) * GPITCH + kb + tg + 4];
                af[mi][3] = As_[(nb + g + 8) * GPITCH + kb + tg + 4];
            }
#pragma unroll
            for (int ni = 0; ni < 4; ni++) {
                const int mb = wn * 32 + ni * 8;
                bf[ni][0] = Ws_[(mb + g) * GPITCH + kb + tg];
                bf[ni][1] = Ws_[(mb + g) * GPITCH + kb + tg + 4];
            }
#pragma unroll
            for (int mi = 0; mi < 4; mi++)
#pragma unroll
                for (int ni = 0; ni < 4; ni++)
                    mma_tf32(acc[mi][ni], af[mi][0], af[mi][1], af[mi][2], af[mi][3],
                             bf[ni][0], bf[ni][1]);
        }

        const int nk = kt + GSTAGES - 1;
        if (nk < KT) {
            const uint32_t sb = (nk % GSTAGES) * GSTAGE_U32 * 4;
            const int k0 = nk * 16;
            cp_async16(aBase + sb + off0, Aptr0 + k0);
            cp_async16(aBase + sb + off1, Aptr1 + k0);
            cp_async16(wBase + sb + off0, Wptr0 + k0);
            cp_async16(wBase + sb + off1, Wptr1 + k0);
        }
        cp_commit();   // unconditional: keeps group count uniform for wait_group 1
    }

#pragma unroll
    for (int mi = 0; mi < 4; mi++) {
#pragma unroll
        for (int ni = 0; ni < 4; ni++) {
#pragma unroll
            for (int c = 0; c < 4; c++) {
                int n = n0 + wm * 64 + mi * 16 + g + ((c >> 1) ? 8 : 0);
                int m = m0 + wn * 32 + ni * 8 + tg * 2 + (c & 1);
                float v = acc[mi][ni][c] + bias[m];
                if (residual) v += residual[(size_t)n * M + m];
                if (flags & FLAG_RELU) v = fmaxf(v, 0.f);
                if (flags & FLAG_HEAD) {
                    int b = n >> 11, s = n & 2047;
                    int h = m >> 6,  dh = m & 63;
                    C[(((size_t)(b * H_ + h)) * S_ + s) * DH_ + dh] = v;
                } else {
                    C[(size_t)n * M + m] = v;
                }
            }
        }
    }
}

// ---------------- flash attention: TF32 QK^T + bf16 PV (register P) ----------------
// CTA: 128 q x 64 k, 256 threads (8 warps), warp w owns rows 16w..16w+15.
#define FAP 68      // tf32 pitch (u32)
#define VPP 36      // bf16-packed V pitch (u32; 32 key-pairs + pad)
#define FA_SMEM ((128 * FAP + 64 * FAP + 64 * VPP) * 4)   // 61440 B

__global__ __launch_bounds__(256, 2)
void flash_tf32(const float* __restrict__ q, const float* __restrict__ k,
                const float* __restrict__ v, const int* __restrict__ mask,
                float* __restrict__ ctx)
{
    extern __shared__ uint32_t sm4[];
    uint32_t* Qs   = sm4;                        // [128 q][d] tf32
    uint32_t* Ks   = sm4 + 128 * FAP;            // [64 kc][d] tf32
    uint32_t* VsTb = sm4 + 192 * FAP;            // [64 d][32 keypair] bf16x2

    const int t = threadIdx.x;
    const int w = t >> 5, lane = t & 31;
    const int g = lane >> 2, tg = lane & 3;
    const int qb = w * 16;
    const int bh = blockIdx.y, b = bh >> 4, h = bh & 15;
    const int q0 = blockIdx.x * 128;
    const float* qh = q + (size_t)bh * S_ * DH_;
    const float* kh = k + (size_t)bh * S_ * DH_;
    const float* vh = v + (size_t)bh * S_ * DH_;
    const int* maskb = mask + (size_t)b * S_ * S_;

    {   // Q tile (128x64) -> smem tf32: row = t>>1, cols [(t&1)*32, +32)
        const int lr = t >> 1, lc = (t & 1) * 32;
        const float4* src4 = (const float4*)(qh + (size_t)(q0 + lr) * 64 + lc);
#pragma unroll
        for (int i = 0; i < 8; i++) {
            float4 a = src4[i];
            uint4 u = { f2tf32(a.x), f2tf32(a.y), f2tf32(a.z), f2tf32(a.w) };
            *(uint4*)&Qs[lr * FAP + lc + i * 4] = u;
        }
    }

    // K loader: 64 rows, 4 threads/row, 16 cols each
    const int krow = t & 63;
    const int kcol = (t >> 6) * 16;
    // V loader: key-pair kp = t&31, d-block db = (t>>5)*8
    const int kp = t & 31;
    const int db = (t >> 5) * 8;

    float outac[8][4];
#pragma unroll
    for (int j = 0; j < 8; j++)
#pragma unroll
        for (int c = 0; c < 4; c++) outac[j][c] = 0.f;
    float mrow0 = -1e30f, mrow1 = -1e30f;
    float lrow0 = 0.f, lrow1 = 0.f;

    for (int k0 = 0; k0 < S_; k0 += 64) {
        __syncthreads();   // prev tile consumed (and Q visible on iter 0)
        {   // K -> tf32 smem
            const float4* ks4 = (const float4*)(kh + (size_t)(k0 + krow) * 64 + kcol);
#pragma unroll
            for (int i = 0; i < 4; i++) {
                float4 a = ks4[i];
                uint4 u = { f2tf32(a.x), f2tf32(a.y), f2tf32(a.z), f2tf32(a.w) };
                *(uint4*)&Ks[krow * FAP + kcol + i * 4] = u;
            }
        }
        {   // V -> bf16x2 transposed: VsTb[d][kp] = (V[2kp][d], V[2kp+1][d])
            const float4* v0 = (const float4*)(vh + (size_t)(k0 + 2 * kp) * 64 + db);
            const float4* v1 = (const float4*)(vh + (size_t)(k0 + 2 * kp + 1) * 64 + db);
            float4 e0 = v0[0], e1 = v0[1];
            float4 o0 = v1[0], o1 = v1[1];
            VsTb[(db + 0) * VPP + kp] = pack_bf16(e0.x, o0.x);
            VsTb[(db + 1) * VPP + kp] = pack_bf16(e0.y, o0.y);
            VsTb[(db + 2) * VPP + kp] = pack_bf16(e0.z, o0.z);
            VsTb[(db + 3) * VPP + kp] = pack_bf16(e0.w, o0.w);
            VsTb[(db + 4) * VPP + kp] = pack_bf16(e1.x, o1.x);
            VsTb[(db + 5) * VPP + kp] = pack_bf16(e1.y, o1.y);
            VsTb[(db + 6) * VPP + kp] = pack_bf16(e1.z, o1.z);
            VsTb[(db + 7) * VPP + kp] = pack_bf16(e1.w, o1.w);
        }
        __syncthreads();

        // S = Q K^T (tf32)
        float sa[8][4];
#pragma unroll
        for (int j = 0; j < 8; j++)
#pragma unroll
            for (int c = 0; c < 4; c++) sa[j][c] = 0.f;
#pragma unroll
        for (int kc = 0; kc < 8; kc++) {
            const int kb = kc * 8;
            uint32_t a0 = Qs[(qb + g) * FAP + kb + tg];
            uint32_t a1 = Qs[(qb + g + 8) * FAP + kb + tg];
            uint32_t a2 = Qs[(qb + g) * FAP + kb + tg + 4];
            uint32_t a3 = Qs[(qb + g + 8) * FAP + kb + tg + 4];
#pragma unroll
            for (int j = 0; j < 8; j++) {
                uint32_t b0 = Ks[(j * 8 + g) * FAP + kb + tg];
                uint32_t b1 = Ks[(j * 8 + g) * FAP + kb + tg + 4];
                mma_tf32(sa[j], a0, a1, a2, a3, b0, b1);
            }
        }

        // scale + mask
        const size_t mrow_a = (size_t)(q0 + qb + g) * S_ + k0;
        const size_t mrow_b = (size_t)(q0 + qb + g + 8) * S_ + k0;
#pragma unroll
        for (int j = 0; j < 8; j++) {
            int col = j * 8 + tg * 2;
            int2 m0 = *(const int2*)&maskb[mrow_a + col];
            int2 m1 = *(const int2*)&maskb[mrow_b + col];
            sa[j][0] = m0.x ? sa[j][0] * 0.125f : -1e9f;
            sa[j][1] = m0.y ? sa[j][1] * 0.125f : -1e9f;
            sa[j][2] = m1.x ? sa[j][2] * 0.125f : -1e9f;
            sa[j][3] = m1.y ? sa[j][3] * 0.125f : -1e9f;
        }

        // online softmax (rows g, g+8), quad reduce
        float mx0 = -1e30f, mx1 = -1e30f;
#pragma unroll
        for (int j = 0; j < 8; j++) {
            mx0 = fmaxf(mx0, fmaxf(sa[j][0], sa[j][1]));
            mx1 = fmaxf(mx1, fmaxf(sa[j][2], sa[j][3]));
        }
        mx0 = fmaxf(mx0, __shfl_xor_sync(0xffffffffu, mx0, 1));
        mx0 = fmaxf(mx0, __shfl_xor_sync(0xffffffffu, mx0, 2));
        mx1 = fmaxf(mx1, __shfl_xor_sync(0xffffffffu, mx1, 1));
        mx1 = fmaxf(mx1, __shfl_xor_sync(0xffffffffu, mx1, 2));

        float mn0 = fmaxf(mrow0, mx0), mn1 = fmaxf(mrow1, mx1);
        float cr0 = fast_exp(mrow0 - mn0), cr1 = fast_exp(mrow1 - mn1);
        mrow0 = mn0; mrow1 = mn1;

        float rs0 = 0.f, rs1 = 0.f;
#pragma unroll
        for (int j = 0; j < 8; j++) {
            sa[j][0] = fast_exp(sa[j][0] - mn0);
            sa[j][1] = fast_exp(sa[j][1] - mn0);
            sa[j][2] = fast_exp(sa[j][2] - mn1);
            sa[j][3] = fast_exp(sa[j][3] - mn1);
            rs0 += sa[j][0] + sa[j][1];
            rs1 += sa[j][2] + sa[j][3];
        }
        rs0 += __shfl_xor_sync(0xffffffffu, rs0, 1);
        rs0 += __shfl_xor_sync(0xffffffffu, rs0, 2);
        rs1 += __shfl_xor_sync(0xffffffffu, rs1, 1);
        rs1 += __shfl_xor_sync(0xffffffffu, rs1, 2);
        lrow0 = lrow0 * cr0 + rs0;
        lrow1 = lrow1 * cr1 + rs1;

#pragma unroll
        for (int j = 0; j < 8; j++) {
            outac[j][0] *= cr0; outac[j][1] *= cr0;
            outac[j][2] *= cr1; outac[j][3] *= cr1;
        }

        // out += P V  — P packed from registers (bf16), V from VsTb
#pragma unroll
        for (int s = 0; s < 4; s++) {
            uint32_t a0 = pack_bf16(sa[2*s][0],   sa[2*s][1]);     // row g,   k 16s+2tg,+1
            uint32_t a1 = pack_bf16(sa[2*s][2],   sa[2*s][3]);     // row g+8
            uint32_t a2 = pack_bf16(sa[2*s+1][0], sa[2*s+1][1]);   // row g,   k 16s+8+2tg
            uint32_t a3 = pack_bf16(sa[2*s+1][2], sa[2*s+1][3]);   // row g+8
            const int kpb = 8 * s;
#pragma unroll
            for (int j = 0; j < 8; j++) {
                uint32_t b0 = VsTb[(j * 8 + g) * VPP + kpb + tg];
                uint32_t b1 = VsTb[(j * 8 + g) * VPP + kpb + tg + 4];
                mma_bf16(outac[j], a0, a1, a2, a3, b0, b1);
            }
        }
    }

    // epilogue
    float i0 = 1.f / lrow0, i1 = 1.f / lrow1;
    const int nrow = b * S_ + q0 + qb + g;
    const int hb = h * 64;
#pragma unroll
    for (int j = 0; j < 8; j++) {
        float2 o0 = { outac[j][0] * i0, outac[j][1] * i0 };
        *(float2*)&ctx[(size_t)nrow * D_ + hb + j * 8 + tg * 2] = o0;
        float2 o1 = { outac[j][2] * i1, outac[j][3] * i1 };
        *(float2*)&ctx[(size_t)(nrow + 8) * D_ + hb + j * 8 + tg * 2] = o1;
    }
}

// ---------------- layer norm (torch semantics: ddof=1, eps on std) ----------------
__global__ void layernorm_kernel(const float* __restrict__ x, const float* __restrict__ alpha,
                                 const float* __restrict__ beta, float* __restrict__ out)
{
    const int row = blockIdx.x;
    const int t = threadIdx.x;
    const float4* xr = (const float4*)(x + (size_t)row * D_);
    float4 v = xr[t];
    float sum = v.x + v.y + v.z + v.w;
    float sq  = v.x * v.x + v.y * v.y + v.z * v.z + v.w * v.w;

    __shared__ float ssum[8], ssq[8];
#pragma unroll
    for (int off = 16; off; off >>= 1) {
        sum += __shfl_xor_sync(0xffffffffu, sum, off);
        sq  += __shfl_xor_sync(0xffffffffu, sq, off);
    }
    int warp = t >> 5, lane = t & 31;
    if (lane == 0) { ssum[warp] = sum; ssq[warp] = sq; }
    __syncthreads();
    float tsum = 0.f, tsq = 0.f;
#pragma unroll
    for (int w = 0; w < 8; w++) { tsum += ssum[w]; tsq += ssq[w]; }

    float mean = tsum * (1.f / D_);
    float var  = (tsq - (float)D_ * mean * mean) * (1.f / (D_ - 1));
    float std_ = sqrtf(fmaxf(var, 0.f));
    float inv  = 1.f / (std_ + EPS_);

    const float4* av = (const float4*)alpha;
    const float4* bv = (const float4*)beta;
    float4 a = av[t], bb = bv[t];
    float4 o;
    o.x = a.x * (v.x - mean) * inv + bb.x;
    o.y = a.y * (v.y - mean) * inv + bb.y;
    o.z = a.z * (v.z - mean) * inv + bb.z;
    o.w = a.w * (v.w - mean) * inv + bb.w;
    ((float4*)(out + (size_t)row * D_))[t] = o;
}

// ---------------- launch ----------------
extern "C" void kernel_launch(void* const* d_in, const int* in_sizes, int n_in,
                              void* d_out, int out_size)
{
    const float* src = (const float*)d_in[0];
    const int*   mask = (const int*)d_in[1];
    const float* Wq = (const float*)d_in[2];
    const float* bq = (const float*)d_in[3];
    const float* Wk = (const float*)d_in[4];
    const float* bk = (const float*)d_in[5];
    const float* Wv = (const float*)d_in[6];
    const float* bv = (const float*)d_in[7];
    const float* Wo = (const float*)d_in[8];
    const float* bo = (const float*)d_in[9];
    const float* W1 = (const float*)d_in[10];
    const float* b1 = (const float*)d_in[11];
    const float* W2 = (const float*)d_in[12];
    const float* b2 = (const float*)d_in[13];
    const float* a1 = (const float*)d_in[14];
    const float* be1 = (const float*)d_in[15];
    const float* a2 = (const float*)d_in[16];
    const float* be2 = (const float*)d_in[17];
    float* out = (float*)d_out;

    void *pq, *pk, *pv, *pctx, *px0, *px1, *pff;
    cudaGetSymbolAddress(&pq, g_q);
    cudaGetSymbolAddress(&pk, g_k);
    cudaGetSymbolAddress(&pv, g_v);
    cudaGetSymbolAddress(&pctx, g_ctx);
    cudaGetSymbolAddress(&px0, g_x0);
    cudaGetSymbolAddress(&px1, g_x1);
    cudaGetSymbolAddress(&pff, g_ff);

    cudaFuncSetAttribute(flash_tf32, cudaFuncAttributeMaxDynamicSharedMemorySize, FA_SMEM);
    cudaFuncSetAttribute(gemm_tf32, cudaFuncAttributeMaxDynamicSharedMemorySize, GEMM_SMEM);

    dim3 blk(256);
    dim3 gD(D_ / 128, N_ / 128);    // (8, 32)
    dim3 gFF(FF_ / 128, N_ / 128);  // (16, 32)

    // QKV projections, stored directly in [B,H,S,Dh] layout
    gemm_tf32<<<gD, blk, GEMM_SMEM>>>(src, Wq, bq, nullptr, (float*)pq, N_, D_, D_, FLAG_HEAD);
    gemm_tf32<<<gD, blk, GEMM_SMEM>>>(src, Wk, bk, nullptr, (float*)pk, N_, D_, D_, FLAG_HEAD);
    gemm_tf32<<<gD, blk, GEMM_SMEM>>>(src, Wv, bv, nullptr, (float*)pv, N_, D_, D_, FLAG_HEAD);

    // attention -> ctx in [N, D] layout
    flash_tf32<<<dim3(S_ / 128, B_ * H_), dim3(256), FA_SMEM>>>(
        (const float*)pq, (const float*)pk, (const float*)pv, mask, (float*)pctx);

    // output projection + residual(src)
    gemm_tf32<<<gD, blk, GEMM_SMEM>>>((const float*)pctx, Wo, bo, src, (float*)px0, N_, D_, D_, 0);

    // norm1
    layernorm_kernel<<<N_, blk>>>((const float*)px0, a1, be1, (float*)px1);

    // FFN
    gemm_tf32<<<gFF, blk, GEMM_SMEM>>>((const float*)px1, W1, b1, nullptr, (float*)pff, N_, FF_, D_, FLAG_RELU);
    gemm_tf32<<<gD, blk, GEMM_SMEM>>>((const float*)pff, W2, b2, (const float*)px1, (float*)px0, N_, D_, FF_, 0);

    // norm2 -> out
    layernorm_kernel<<<N_, blk>>>((const float*)px0, a2, be2, out);
}